// round 1
// baseline (speedup 1.0000x reference)
#include <cuda_runtime.h>
#include <cuda_bf16.h>
#include <math.h>

// Problem constants (from reference): E=128, H=4, hd=32.
#define EDIM   128
#define NHEAD  4
#define HD     32
#define MAXN   65536
#define MAXB   512
#define MAXT   (MAXN + MAXB)     // 66048 packed tokens
#define LCAP   320               // smem staging cap per (graph,head); global fallback beyond

// ---------------- scratch (device globals; no allocation allowed) ----------------
__device__ float g_value[(size_t)MAXT * EDIM];
__device__ float g_kin  [(size_t)MAXT * EDIM];
__device__ float g_qin  [(size_t)MAXT * EDIM];
__device__ float g_q    [(size_t)MAXT * EDIM];
__device__ float g_k    [(size_t)MAXT * EDIM];
__device__ float g_v    [(size_t)MAXT * EDIM];
__device__ float g_ctx  [(size_t)MAXT * EDIM];
__device__ int   g_off  [MAXB + 1];
__device__ int   g_dest [MAXT];

// ---------------- offsets: lower_bound per graph over sorted batch ----------------
__global__ void offsets_kernel(const int* __restrict__ batch, int N, int nB, int* __restrict__ off)
{
    int g = blockIdx.x * blockDim.x + threadIdx.x;
    if (g > nB) return;
    if (g == nB) { off[nB] = N; return; }
    int lo = 0, hi = N;
    while (lo < hi) {
        int mid = (lo + hi) >> 1;
        if (batch[mid] < g) lo = mid + 1; else hi = mid;
    }
    off[g] = lo;
}

// ---------------- gather packed value + dest map ----------------
// token layout: graph g occupies [off[g]+g, off[g]+g+count+1); slot 0 = metal token.
// node i  -> token i + batch[i] + 1, dest row = i
// metal g -> token off[g] + g,      dest row = N + g
__global__ void gather_kernel(const float* __restrict__ x, const float* __restrict__ mx,
                              const int* __restrict__ batch, const int* __restrict__ off,
                              int N, int nB,
                              float* __restrict__ value, int* __restrict__ dest)
{
    int row  = blockIdx.x * 8 + (threadIdx.x >> 5);
    int lane = threadIdx.x & 31;
    if (row < N) {
        int g   = batch[row];
        int tok = row + g + 1;
        float4 v4 = *(const float4*)(x + (size_t)row * EDIM + lane * 4);
        *(float4*)(value + (size_t)tok * EDIM + lane * 4) = v4;
        if (lane == 0) dest[tok] = row;
    } else if (row < N + nB) {
        int g   = row - N;
        int tok = off[g] + g;
        float4 v4 = *(const float4*)(mx + (size_t)g * EDIM + lane * 4);
        *(float4*)(value + (size_t)tok * EDIM + lane * 4) = v4;
        if (lane == 0) dest[tok] = N + g;
    }
}

// ---------------- GEMM: C[t][o] = act( sum_k A[t][k] * W[o][k] + bias[o] ) ----------------
// Tile 128x128, K=128 fully resident. 256 threads, 8x8 per thread.
// Both tiles stored k-major with pitch 132 for conflict-free broadcast reads.
#define GPITCH 132
#define GEMM_SMEM (2 * 128 * GPITCH * 4)

__global__ void gemm128_kernel(const float* __restrict__ A, const float* __restrict__ W,
                               const float* __restrict__ bias, float* __restrict__ C,
                               const int* __restrict__ dest, int T, int doRelu)
{
    extern __shared__ float sm[];
    float* As = sm;                    // As[k*GPITCH + t]
    float* Ws = sm + 128 * GPITCH;     // Ws[k*GPITCH + o]

    int tile0 = blockIdx.x * 128;
    int tid   = threadIdx.x;

    // load: threads 0..127 -> half 0 (k 0..63), 128..255 -> half 1 (k 64..127)
    {
        int row  = tid & 127;
        int half = tid >> 7;
        bool valid = (tile0 + row) < T;
        const float* Arow = A + (size_t)(tile0 + row) * EDIM + half * 64;
        const float* Wrow = W + (size_t)row * EDIM + half * 64;
        #pragma unroll
        for (int vq = 0; vq < 16; vq++) {
            int k0 = half * 64 + vq * 4;
            float4 av = valid ? *(const float4*)(Arow + vq * 4) : make_float4(0.f, 0.f, 0.f, 0.f);
            As[(k0 + 0) * GPITCH + row] = av.x;
            As[(k0 + 1) * GPITCH + row] = av.y;
            As[(k0 + 2) * GPITCH + row] = av.z;
            As[(k0 + 3) * GPITCH + row] = av.w;
            float4 wv = *(const float4*)(Wrow + vq * 4);
            Ws[(k0 + 0) * GPITCH + row] = wv.x;
            Ws[(k0 + 1) * GPITCH + row] = wv.y;
            Ws[(k0 + 2) * GPITCH + row] = wv.z;
            Ws[(k0 + 3) * GPITCH + row] = wv.w;
        }
    }
    __syncthreads();

    int tx = tid & 15, ty = tid >> 4;
    float acc[8][8];
    #pragma unroll
    for (int i = 0; i < 8; i++)
        #pragma unroll
        for (int j = 0; j < 8; j++) acc[i][j] = 0.f;

    #pragma unroll 4
    for (int kk = 0; kk < 128; kk++) {
        float4 a0 = *(const float4*)&As[kk * GPITCH + ty * 8];
        float4 a1 = *(const float4*)&As[kk * GPITCH + ty * 8 + 4];
        float4 w0 = *(const float4*)&Ws[kk * GPITCH + tx * 8];
        float4 w1 = *(const float4*)&Ws[kk * GPITCH + tx * 8 + 4];
        float a[8] = {a0.x, a0.y, a0.z, a0.w, a1.x, a1.y, a1.z, a1.w};
        float w[8] = {w0.x, w0.y, w0.z, w0.w, w1.x, w1.y, w1.z, w1.w};
        #pragma unroll
        for (int i = 0; i < 8; i++)
            #pragma unroll
            for (int j = 0; j < 8; j++) acc[i][j] += a[i] * w[j];
    }

    float bv[8];
    #pragma unroll
    for (int j = 0; j < 8; j++) bv[j] = bias ? bias[tx * 8 + j] : 0.f;

    #pragma unroll
    for (int i = 0; i < 8; i++) {
        int r = tile0 + ty * 8 + i;
        if (r >= T) continue;
        int orow = dest ? dest[r] : r;
        float* Crow = C + (size_t)orow * EDIM + tx * 8;
        float4 o0, o1;
        float t0v = acc[i][0] + bv[0], t1v = acc[i][1] + bv[1];
        float t2v = acc[i][2] + bv[2], t3v = acc[i][3] + bv[3];
        float t4v = acc[i][4] + bv[4], t5v = acc[i][5] + bv[5];
        float t6v = acc[i][6] + bv[6], t7v = acc[i][7] + bv[7];
        if (doRelu) {
            t0v = fmaxf(t0v, 0.f); t1v = fmaxf(t1v, 0.f);
            t2v = fmaxf(t2v, 0.f); t3v = fmaxf(t3v, 0.f);
            t4v = fmaxf(t4v, 0.f); t5v = fmaxf(t5v, 0.f);
            t6v = fmaxf(t6v, 0.f); t7v = fmaxf(t7v, 0.f);
        }
        o0 = make_float4(t0v, t1v, t2v, t3v);
        o1 = make_float4(t4v, t5v, t6v, t7v);
        *(float4*)(Crow)     = o0;
        *(float4*)(Crow + 4) = o1;
    }
}

// ---------------- attention: one block per (graph, head) ----------------
#define ATTN_SMEM (2 * LCAP * HD * 4)

__global__ void attn_kernel(const float* __restrict__ q, const float* __restrict__ k,
                            const float* __restrict__ v, float* __restrict__ ctx,
                            const int* __restrict__ off)
{
    extern __shared__ float sm[];
    float* Ks = sm;
    float* Vs = sm + LCAP * HD;

    int g = blockIdx.x, h = blockIdx.y;
    int t0 = off[g] + g;
    int L  = off[g + 1] - off[g] + 1;
    int Ls = L < LCAP ? L : LCAP;
    int tid = threadIdx.x;

    for (int idx = tid; idx < Ls * 8; idx += blockDim.x) {
        int m  = idx >> 3;
        int j4 = (idx & 7) * 4;
        const float* kp = k + (size_t)(t0 + m) * EDIM + h * HD + j4;
        const float* vp = v + (size_t)(t0 + m) * EDIM + h * HD + j4;
        *(float4*)(Ks + m * HD + j4) = *(const float4*)kp;
        *(float4*)(Vs + m * HD + j4) = *(const float4*)vp;
    }
    __syncthreads();

    const float scale = 0.17677669529663688f; // 1/sqrt(32)

    for (int qi = tid; qi < L; qi += blockDim.x) {
        float qr[32];
        const float* qp = q + (size_t)(t0 + qi) * EDIM + h * HD;
        #pragma unroll
        for (int j4 = 0; j4 < 8; j4++) {
            float4 t4 = *(const float4*)(qp + j4 * 4);
            qr[j4 * 4 + 0] = t4.x; qr[j4 * 4 + 1] = t4.y;
            qr[j4 * 4 + 2] = t4.z; qr[j4 * 4 + 3] = t4.w;
        }
        float mx = -1e30f, s = 0.f;
        float acc[32];
        #pragma unroll
        for (int j = 0; j < 32; j++) acc[j] = 0.f;

        for (int mk = 0; mk < L; mk++) {
            const float* kp = (mk < LCAP) ? (Ks + mk * HD)
                                          : (k + (size_t)(t0 + mk) * EDIM + h * HD);
            const float* vp = (mk < LCAP) ? (Vs + mk * HD)
                                          : (v + (size_t)(t0 + mk) * EDIM + h * HD);
            float dot = 0.f;
            #pragma unroll
            for (int j4 = 0; j4 < 8; j4++) {
                float4 k4 = *(const float4*)(kp + j4 * 4);
                dot += qr[j4 * 4 + 0] * k4.x;
                dot += qr[j4 * 4 + 1] * k4.y;
                dot += qr[j4 * 4 + 2] * k4.z;
                dot += qr[j4 * 4 + 3] * k4.w;
            }
            float xv = dot * scale;
            if (xv > mx) {
                float corr = __expf(mx - xv);
                s *= corr;
                #pragma unroll
                for (int j = 0; j < 32; j++) acc[j] *= corr;
                mx = xv;
            }
            float p = __expf(xv - mx);
            s += p;
            #pragma unroll
            for (int j4 = 0; j4 < 8; j4++) {
                float4 v4 = *(const float4*)(vp + j4 * 4);
                acc[j4 * 4 + 0] += p * v4.x;
                acc[j4 * 4 + 1] += p * v4.y;
                acc[j4 * 4 + 2] += p * v4.z;
                acc[j4 * 4 + 3] += p * v4.w;
            }
        }
        float inv = 1.f / s;
        float* cp = ctx + (size_t)(t0 + qi) * EDIM + h * HD;
        #pragma unroll
        for (int j4 = 0; j4 < 8; j4++) {
            float4 o4 = make_float4(acc[j4 * 4 + 0] * inv, acc[j4 * 4 + 1] * inv,
                                    acc[j4 * 4 + 2] * inv, acc[j4 * 4 + 3] * inv);
            *(float4*)(cp + j4 * 4) = o4;
        }
    }
}

// ---------------- launch ----------------
extern "C" void kernel_launch(void* const* d_in, const int* in_sizes, int n_in,
                              void* d_out, int out_size)
{
    const float* x       = (const float*)d_in[0];
    const float* metal_x = (const float*)d_in[1];
    const int*   batch   = (const int*)  d_in[2];
    const float* Wk      = (const float*)d_in[3];
    const float* bk      = (const float*)d_in[4];
    const float* Wq      = (const float*)d_in[5];
    const float* bq      = (const float*)d_in[6];
    const float* in_w    = (const float*)d_in[7];
    const float* in_b    = (const float*)d_in[8];
    const float* out_w   = (const float*)d_in[9];
    const float* out_b   = (const float*)d_in[10];
    float* out = (float*)d_out;

    int N  = in_sizes[0] / EDIM;
    int nB = in_sizes[1] / EDIM;
    int T  = N + nB;

    // resolve scratch symbols
    float *value, *kin, *qin, *qb, *kb, *vb, *ctx;
    int *off, *dest;
    cudaGetSymbolAddress((void**)&value, g_value);
    cudaGetSymbolAddress((void**)&kin,   g_kin);
    cudaGetSymbolAddress((void**)&qin,   g_qin);
    cudaGetSymbolAddress((void**)&qb,    g_q);
    cudaGetSymbolAddress((void**)&kb,    g_k);
    cudaGetSymbolAddress((void**)&vb,    g_v);
    cudaGetSymbolAddress((void**)&ctx,   g_ctx);
    cudaGetSymbolAddress((void**)&off,   g_off);
    cudaGetSymbolAddress((void**)&dest,  g_dest);

    cudaFuncSetAttribute(gemm128_kernel, cudaFuncAttributeMaxDynamicSharedMemorySize, GEMM_SMEM);
    cudaFuncSetAttribute(attn_kernel,    cudaFuncAttributeMaxDynamicSharedMemorySize, ATTN_SMEM);

    // 1. offsets
    offsets_kernel<<<(nB + 256) / 256, 256>>>(batch, N, nB, off);

    // 2. gather packed tokens
    gather_kernel<<<(T + 7) / 8, 256>>>(x, metal_x, batch, off, N, nB, value, dest);

    int gblocks = (T + 127) / 128;

    // 3-7. projections
    gemm128_kernel<<<gblocks, 256, GEMM_SMEM>>>(value, Wk, bk, kin, nullptr, T, 1);
    gemm128_kernel<<<gblocks, 256, GEMM_SMEM>>>(value, Wq, bq, qin, nullptr, T, 1);
    gemm128_kernel<<<gblocks, 256, GEMM_SMEM>>>(qin,   in_w,                 in_b,           qb, nullptr, T, 0);
    gemm128_kernel<<<gblocks, 256, GEMM_SMEM>>>(kin,   in_w + EDIM * EDIM,   in_b + EDIM,    kb, nullptr, T, 0);
    gemm128_kernel<<<gblocks, 256, GEMM_SMEM>>>(value, in_w + 2 * EDIM * EDIM, in_b + 2 * EDIM, vb, nullptr, T, 0);

    // 8. per-graph per-head attention
    dim3 agrid(nB, NHEAD);
    attn_kernel<<<agrid, 128, ATTN_SMEM>>>(qb, kb, vb, ctx, off);

    // 9. out projection fused with scatter to d_out (x_out rows 0..N-1, metal rows N..N+B-1)
    gemm128_kernel<<<gblocks, 256, GEMM_SMEM>>>(ctx, out_w, out_b, out, dest, T, 0);
}

// round 2
// speedup vs baseline: 1.1462x; 1.1462x over previous
#include <cuda_runtime.h>
#include <cuda_bf16.h>
#include <math.h>

// Problem constants: E=128, H=4, hd=32.
#define EDIM   128
#define NHEAD  4
#define HD     32
#define MAXN   65536
#define MAXB   512
#define MAXT   (MAXN + MAXB)     // 66048 packed tokens
#define LCAP   320               // smem staging cap per (graph,head); global fallback beyond

// ---------------- scratch (device globals; no allocation allowed) ----------------
__device__ float g_value[(size_t)MAXT * EDIM];
__device__ float g_kin  [(size_t)MAXT * EDIM];
__device__ float g_qin  [(size_t)MAXT * EDIM];
__device__ float g_q    [(size_t)MAXT * EDIM];   // head-major [H][T][HD]
__device__ float g_k    [(size_t)MAXT * EDIM];   // head-major [H][T][HD]
__device__ float g_v    [(size_t)MAXT * EDIM];   // head-major [H][T][HD]
__device__ float g_ctx  [(size_t)MAXT * EDIM];   // token-major [T][E]
__device__ int   g_off  [MAXB + 1];
__device__ int   g_dest [MAXT];

// ---------------- offsets: lower_bound per graph over sorted batch ----------------
__global__ void offsets_kernel(const int* __restrict__ batch, int N, int nB, int* __restrict__ off)
{
    int g = blockIdx.x * blockDim.x + threadIdx.x;
    if (g > nB) return;
    if (g == nB) { off[nB] = N; return; }
    int lo = 0, hi = N;
    while (lo < hi) {
        int mid = (lo + hi) >> 1;
        if (batch[mid] < g) lo = mid + 1; else hi = mid;
    }
    off[g] = lo;
}

// ---------------- gather packed value + dest map ----------------
__global__ void gather_kernel(const float* __restrict__ x, const float* __restrict__ mx,
                              const int* __restrict__ batch, const int* __restrict__ off,
                              int N, int nB,
                              float* __restrict__ value, int* __restrict__ dest)
{
    int row  = blockIdx.x * 8 + (threadIdx.x >> 5);
    int lane = threadIdx.x & 31;
    if (row < N) {
        int g   = batch[row];
        int tok = row + g + 1;
        float4 v4 = *(const float4*)(x + (size_t)row * EDIM + lane * 4);
        *(float4*)(value + (size_t)tok * EDIM + lane * 4) = v4;
        if (lane == 0) dest[tok] = row;
    } else if (row < N + nB) {
        int g   = row - N;
        int tok = off[g] + g;
        float4 v4 = *(const float4*)(mx + (size_t)g * EDIM + lane * 4);
        *(float4*)(value + (size_t)tok * EDIM + lane * 4) = v4;
        if (lane == 0) dest[tok] = N + g;
    }
}

// ---------------- GEMM: C = act(A @ W^T + b), 128x128 tile, K=128 resident ----------------
// 512 threads: 8 rows x 4 cols per thread. k-major smem, pitch 132.
// headMode: write output head-major [H][T][HD] instead of token-major.
#define GPITCH 132
#define GEMM_SMEM (2 * 128 * GPITCH * 4)

__global__ __launch_bounds__(512, 1)
void gemm128_kernel(const float* __restrict__ A, const float* __restrict__ W,
                    const float* __restrict__ bias, float* __restrict__ C,
                    const int* __restrict__ dest, int T, int doRelu, int headMode)
{
    extern __shared__ float sm[];
    float* As = sm;                    // As[k*GPITCH + t]
    float* Ws = sm + 128 * GPITCH;     // Ws[k*GPITCH + o]

    int tile0 = blockIdx.x * 128;
    int tid   = threadIdx.x;

    // stage tiles: thread -> (row = tid&127, k-quarter = tid>>7), 8 float4 each of A and W
    {
        int row = tid & 127;
        int qk  = tid >> 7;            // 0..3
        bool valid = (tile0 + row) < T;
        const float* Arow = A + (size_t)(tile0 + row) * EDIM + qk * 32;
        const float* Wrow = W + (size_t)row * EDIM + qk * 32;
        #pragma unroll
        for (int vq = 0; vq < 8; vq++) {
            int k0 = qk * 32 + vq * 4;
            float4 av = valid ? *(const float4*)(Arow + vq * 4) : make_float4(0.f,0.f,0.f,0.f);
            As[(k0 + 0) * GPITCH + row] = av.x;
            As[(k0 + 1) * GPITCH + row] = av.y;
            As[(k0 + 2) * GPITCH + row] = av.z;
            As[(k0 + 3) * GPITCH + row] = av.w;
            float4 wv = *(const float4*)(Wrow + vq * 4);
            Ws[(k0 + 0) * GPITCH + row] = wv.x;
            Ws[(k0 + 1) * GPITCH + row] = wv.y;
            Ws[(k0 + 2) * GPITCH + row] = wv.z;
            Ws[(k0 + 3) * GPITCH + row] = wv.w;
        }
    }
    __syncthreads();

    int tx = tid & 31;       // col group (4 cols)
    int ty = tid >> 5;       // row group (8 rows); uniform within a warp -> A loads broadcast
    float acc[8][4];
    #pragma unroll
    for (int i = 0; i < 8; i++)
        #pragma unroll
        for (int j = 0; j < 4; j++) acc[i][j] = 0.f;

    #pragma unroll 8
    for (int kk = 0; kk < 128; kk++) {
        float4 a0 = *(const float4*)&As[kk * GPITCH + ty * 8];
        float4 a1 = *(const float4*)&As[kk * GPITCH + ty * 8 + 4];
        float4 w0 = *(const float4*)&Ws[kk * GPITCH + tx * 4];
        float a[8] = {a0.x, a0.y, a0.z, a0.w, a1.x, a1.y, a1.z, a1.w};
        float w[4] = {w0.x, w0.y, w0.z, w0.w};
        #pragma unroll
        for (int i = 0; i < 8; i++)
            #pragma unroll
            for (int j = 0; j < 4; j++) acc[i][j] += a[i] * w[j];
    }

    float bv[4];
    #pragma unroll
    for (int j = 0; j < 4; j++) bv[j] = bias ? bias[tx * 4 + j] : 0.f;

    #pragma unroll
    for (int i = 0; i < 8; i++) {
        int r = tile0 + ty * 8 + i;
        if (r >= T) continue;
        float o0 = acc[i][0] + bv[0], o1 = acc[i][1] + bv[1];
        float o2 = acc[i][2] + bv[2], o3 = acc[i][3] + bv[3];
        if (doRelu) {
            o0 = fmaxf(o0, 0.f); o1 = fmaxf(o1, 0.f);
            o2 = fmaxf(o2, 0.f); o3 = fmaxf(o3, 0.f);
        }
        float4 ov = make_float4(o0, o1, o2, o3);
        if (headMode) {
            int c0 = tx * 4;
            int h  = c0 >> 5;
            int ci = c0 & 31;
            *(float4*)(C + ((size_t)h * T + r) * HD + ci) = ov;
        } else {
            int orow = dest ? dest[r] : r;
            *(float4*)(C + (size_t)orow * EDIM + tx * 4) = ov;
        }
    }
}

// ---------------- attention: one block per (graph, head), head-major q/k/v ----------------
#define ATTN_SMEM (2 * LCAP * HD * 4)

__global__ __launch_bounds__(128)
void attn_kernel(const float* __restrict__ q, const float* __restrict__ k,
                 const float* __restrict__ v, float* __restrict__ ctx,
                 const int* __restrict__ off, int T)
{
    extern __shared__ float sm[];
    float* Ks = sm;
    float* Vs = sm + LCAP * HD;

    int g = blockIdx.x, h = blockIdx.y;
    int t0 = off[g] + g;
    int L  = off[g + 1] - off[g] + 1;
    int Ls = L < LCAP ? L : LCAP;
    int tid = threadIdx.x;

    const float* kh = k + (size_t)h * T * HD;
    const float* vh = v + (size_t)h * T * HD;
    const float* qh = q + (size_t)h * T * HD;

    // fully coalesced staging: [Ls][32] contiguous slabs
    for (int idx = tid; idx < Ls * 8; idx += blockDim.x) {
        *(float4*)(Ks + idx * 4) = *(const float4*)(kh + (size_t)t0 * HD + idx * 4);
        *(float4*)(Vs + idx * 4) = *(const float4*)(vh + (size_t)t0 * HD + idx * 4);
    }
    __syncthreads();

    const float scale = 0.17677669529663688f; // 1/sqrt(32)

    for (int qi = tid; qi < L; qi += blockDim.x) {
        float qr[32];
        const float* qp = qh + (size_t)(t0 + qi) * HD;
        #pragma unroll
        for (int j4 = 0; j4 < 8; j4++) {
            float4 t4 = *(const float4*)(qp + j4 * 4);
            qr[j4 * 4 + 0] = t4.x * scale; qr[j4 * 4 + 1] = t4.y * scale;
            qr[j4 * 4 + 2] = t4.z * scale; qr[j4 * 4 + 3] = t4.w * scale;
        }
        float mx = -1e30f, s = 0.f;
        float acc[32];
        #pragma unroll
        for (int j = 0; j < 32; j++) acc[j] = 0.f;

        for (int mk = 0; mk < L; mk++) {
            const float* kp = (mk < Ls) ? (Ks + mk * HD)
                                        : (kh + (size_t)(t0 + mk) * HD);
            // 4-way ILP dot
            float d0 = 0.f, d1 = 0.f, d2 = 0.f, d3 = 0.f;
            #pragma unroll
            for (int j4 = 0; j4 < 8; j4++) {
                float4 k4 = *(const float4*)(kp + j4 * 4);
                d0 += qr[j4 * 4 + 0] * k4.x;
                d1 += qr[j4 * 4 + 1] * k4.y;
                d2 += qr[j4 * 4 + 2] * k4.z;
                d3 += qr[j4 * 4 + 3] * k4.w;
            }
            float xv = (d0 + d1) + (d2 + d3);

            // branch-free online softmax update
            float nm = fmaxf(mx, xv);
            float c  = __expf(mx - nm);
            float p  = __expf(xv - nm);
            mx = nm;
            s  = s * c + p;

            const float* vp = (mk < Ls) ? (Vs + mk * HD)
                                        : (vh + (size_t)(t0 + mk) * HD);
            #pragma unroll
            for (int j4 = 0; j4 < 8; j4++) {
                float4 v4 = *(const float4*)(vp + j4 * 4);
                acc[j4 * 4 + 0] = acc[j4 * 4 + 0] * c + p * v4.x;
                acc[j4 * 4 + 1] = acc[j4 * 4 + 1] * c + p * v4.y;
                acc[j4 * 4 + 2] = acc[j4 * 4 + 2] * c + p * v4.z;
                acc[j4 * 4 + 3] = acc[j4 * 4 + 3] * c + p * v4.w;
            }
        }
        float inv = 1.f / s;
        float* cp = ctx + (size_t)(t0 + qi) * EDIM + h * HD;   // token-major for out_proj
        #pragma unroll
        for (int j4 = 0; j4 < 8; j4++) {
            float4 o4 = make_float4(acc[j4 * 4 + 0] * inv, acc[j4 * 4 + 1] * inv,
                                    acc[j4 * 4 + 2] * inv, acc[j4 * 4 + 3] * inv);
            *(float4*)(cp + j4 * 4) = o4;
        }
    }
}

// ---------------- launch ----------------
extern "C" void kernel_launch(void* const* d_in, const int* in_sizes, int n_in,
                              void* d_out, int out_size)
{
    const float* x       = (const float*)d_in[0];
    const float* metal_x = (const float*)d_in[1];
    const int*   batch   = (const int*)  d_in[2];
    const float* Wk      = (const float*)d_in[3];
    const float* bk      = (const float*)d_in[4];
    const float* Wq      = (const float*)d_in[5];
    const float* bq      = (const float*)d_in[6];
    const float* in_w    = (const float*)d_in[7];
    const float* in_b    = (const float*)d_in[8];
    const float* out_w   = (const float*)d_in[9];
    const float* out_b   = (const float*)d_in[10];
    float* out = (float*)d_out;

    int N  = in_sizes[0] / EDIM;
    int nB = in_sizes[1] / EDIM;
    int T  = N + nB;

    float *value, *kin, *qin, *qb, *kb, *vb, *ctx;
    int *off, *dest;
    cudaGetSymbolAddress((void**)&value, g_value);
    cudaGetSymbolAddress((void**)&kin,   g_kin);
    cudaGetSymbolAddress((void**)&qin,   g_qin);
    cudaGetSymbolAddress((void**)&qb,    g_q);
    cudaGetSymbolAddress((void**)&kb,    g_k);
    cudaGetSymbolAddress((void**)&vb,    g_v);
    cudaGetSymbolAddress((void**)&ctx,   g_ctx);
    cudaGetSymbolAddress((void**)&off,   g_off);
    cudaGetSymbolAddress((void**)&dest,  g_dest);

    cudaFuncSetAttribute(gemm128_kernel, cudaFuncAttributeMaxDynamicSharedMemorySize, GEMM_SMEM);
    cudaFuncSetAttribute(attn_kernel,    cudaFuncAttributeMaxDynamicSharedMemorySize, ATTN_SMEM);

    // 1. offsets
    offsets_kernel<<<(nB + 256) / 256, 256>>>(batch, N, nB, off);

    // 2. gather packed tokens
    gather_kernel<<<(T + 7) / 8, 256>>>(x, metal_x, batch, off, N, nB, value, dest);

    int gblocks = (T + 127) / 128;

    // 3-7. projections (q/k/v written head-major)
    gemm128_kernel<<<gblocks, 512, GEMM_SMEM>>>(value, Wk, bk, kin, nullptr, T, 1, 0);
    gemm128_kernel<<<gblocks, 512, GEMM_SMEM>>>(value, Wq, bq, qin, nullptr, T, 1, 0);
    gemm128_kernel<<<gblocks, 512, GEMM_SMEM>>>(qin,   in_w,                   in_b,            qb, nullptr, T, 0, 1);
    gemm128_kernel<<<gblocks, 512, GEMM_SMEM>>>(kin,   in_w + EDIM * EDIM,     in_b + EDIM,     kb, nullptr, T, 0, 1);
    gemm128_kernel<<<gblocks, 512, GEMM_SMEM>>>(value, in_w + 2 * EDIM * EDIM, in_b + 2 * EDIM, vb, nullptr, T, 0, 1);

    // 8. per-graph per-head attention
    dim3 agrid(nB, NHEAD);
    attn_kernel<<<agrid, 128, ATTN_SMEM>>>(qb, kb, vb, ctx, off, T);

    // 9. out projection fused with scatter to d_out
    gemm128_kernel<<<gblocks, 512, GEMM_SMEM>>>(ctx, out_w, out_b, out, dest, T, 0, 0);
}

// round 4
// speedup vs baseline: 1.5979x; 1.3940x over previous
#include <cuda_runtime.h>
#include <cuda_bf16.h>
#include <cstdint>

#define EDIM   128
#define NHEAD  4
#define HD     32
#define MAXN   65536
#define MAXB   512
#define MAXT   (MAXN + MAXB)
#define LCAP   192

// ---------------- scratch ----------------
__device__ float g_value[(size_t)MAXT * EDIM];
__device__ float g_kin  [(size_t)MAXT * EDIM];
__device__ float g_qin  [(size_t)MAXT * EDIM];
__device__ float g_q    [(size_t)MAXT * EDIM];   // head-major [H][T][HD]
__device__ float g_k    [(size_t)MAXT * EDIM];
__device__ float g_v    [(size_t)MAXT * EDIM];
__device__ float g_ctx  [(size_t)MAXT * EDIM];
__device__ __nv_bfloat16 g_wbhi[6 * EDIM * EDIM];  // bf16-hi weights: Wk,Wq,inq,ink,inv,out
__device__ __nv_bfloat16 g_wblo[6 * EDIM * EDIM];
__device__ int   g_off  [MAXB + 1];
__device__ int   g_dest [MAXT];

// ---------------- helpers ----------------
__device__ __forceinline__ uint32_t smem_u32(const void* p) {
    uint32_t a;
    asm("{ .reg .u64 t; cvta.to.shared.u64 t, %1; cvt.u32.u64 %0, t; }" : "=r"(a) : "l"(p));
    return a;
}
__device__ __forceinline__ void ldsm4(uint32_t* r, uint32_t addr) {
    asm volatile("ldmatrix.sync.aligned.m8n8.x4.shared.b16 {%0,%1,%2,%3}, [%4];"
                 : "=r"(r[0]), "=r"(r[1]), "=r"(r[2]), "=r"(r[3]) : "r"(addr));
}
__device__ __forceinline__ void mma_bf16(float* d, const uint32_t* a, const uint32_t* b) {
    asm volatile("mma.sync.aligned.m16n8k16.row.col.f32.bf16.bf16.f32 "
                 "{%0,%1,%2,%3}, {%4,%5,%6,%7}, {%8,%9}, {%0,%1,%2,%3};"
                 : "+f"(d[0]), "+f"(d[1]), "+f"(d[2]), "+f"(d[3])
                 : "r"(a[0]), "r"(a[1]), "r"(a[2]), "r"(a[3]), "r"(b[0]), "r"(b[1]));
}
__device__ __forceinline__ uint32_t pack_bf2(float a, float b) {
    __nv_bfloat162 t = __floats2bfloat162_rn(a, b);
    return *(uint32_t*)&t;
}

// ---------------- small setup kernels ----------------
__global__ void offsets_kernel(const int* __restrict__ batch, int N, int nB, int* __restrict__ off)
{
    int g = blockIdx.x * blockDim.x + threadIdx.x;
    if (g > nB) return;
    if (g == nB) { off[nB] = N; return; }
    int lo = 0, hi = N;
    while (lo < hi) { int m = (lo + hi) >> 1; if (batch[m] < g) lo = m + 1; else hi = m; }
    off[g] = lo;
}

__global__ void gather_kernel(const float* __restrict__ x, const float* __restrict__ mx,
                              const int* __restrict__ batch, const int* __restrict__ off,
                              int N, int nB, float* __restrict__ value, int* __restrict__ dest)
{
    int row  = blockIdx.x * 8 + (threadIdx.x >> 5);
    int lane = threadIdx.x & 31;
    if (row < N) {
        int g = batch[row]; int tok = row + g + 1;
        float4 v4 = *(const float4*)(x + (size_t)row * EDIM + lane * 4);
        *(float4*)(value + (size_t)tok * EDIM + lane * 4) = v4;
        if (lane == 0) dest[tok] = row;
    } else if (row < N + nB) {
        int g = row - N; int tok = off[g] + g;
        float4 v4 = *(const float4*)(mx + (size_t)g * EDIM + lane * 4);
        *(float4*)(value + (size_t)tok * EDIM + lane * 4) = v4;
        if (lane == 0) dest[tok] = N + g;
    }
}

// decompose weights into bf16 hi/lo, packed [Wk, Wq, in_q, in_k, in_v, out_w]
__global__ void wdecomp_kernel(const float* __restrict__ Wk, const float* __restrict__ Wq,
                               const float* __restrict__ in_w, const float* __restrict__ out_w,
                               __nv_bfloat16* __restrict__ bhi, __nv_bfloat16* __restrict__ blo)
{
    int idx = blockIdx.x * 256 + threadIdx.x;
    if (idx >= 6 * EDIM * EDIM) return;
    int slab = idx >> 14, r = idx & 16383;
    float v = (slab == 0) ? Wk[r] : (slab == 1) ? Wq[r]
            : (slab < 5)  ? in_w[(size_t)(slab - 2) * EDIM * EDIM + r] : out_w[r];
    __nv_bfloat16 h = __float2bfloat16(v);
    float hf = __bfloat162float(h);
    bhi[idx] = h;
    blo[idx] = __float2bfloat16(v - hf);
}

// ---------------- mma.sync GEMM: C = act(A @ W^T + bias), 3xBF16 ----------------
// 128x128 tile, K=128 resident. 256 thr = 8 warps (2 M x 4 N), warp tile 64x32.
// MODE: 0=token-major, 1=head-major [H][T][HD], 2=dest scatter.
#define SA_HI 0
#define SA_LO 32768
#define SB_HI 65536
#define SB_LO 98304
#define GEMM_SMEM 131072

template<int RELU, int MODE>
__global__ __launch_bounds__(256, 1)
void gemm_mma(const float* __restrict__ A,
              const __nv_bfloat16* __restrict__ Bhi, const __nv_bfloat16* __restrict__ Blo,
              const float* __restrict__ bias, float* __restrict__ C,
              const int* __restrict__ dest, int T)
{
    extern __shared__ char smem[];
    const uint32_t sb = smem_u32(smem);
    const int tid  = threadIdx.x;
    const int wid  = tid >> 5, lane = tid & 31;
    const int tile0 = blockIdx.x * 128;

    // ---- stage A (fp32 -> bf16 hi/lo, swizzled 16B chunks) ----
    #pragma unroll
    for (int i = 0; i < 8; i++) {
        int f   = tid + i * 256;          // 0..2047
        int row = f >> 4;
        int grp = f & 15;                 // 8-float group -> one 16B bf16 chunk
        float4 v0 = make_float4(0.f,0.f,0.f,0.f), v1 = v0;
        if (tile0 + row < T) {
            const float* p = A + (size_t)(tile0 + row) * EDIM + grp * 8;
            v0 = *(const float4*)p;
            v1 = *(const float4*)(p + 4);
        }
        float h0 = __bfloat162float(__float2bfloat16(v0.x));
        float h1 = __bfloat162float(__float2bfloat16(v0.y));
        float h2 = __bfloat162float(__float2bfloat16(v0.z));
        float h3 = __bfloat162float(__float2bfloat16(v0.w));
        float h4 = __bfloat162float(__float2bfloat16(v1.x));
        float h5 = __bfloat162float(__float2bfloat16(v1.y));
        float h6 = __bfloat162float(__float2bfloat16(v1.z));
        float h7 = __bfloat162float(__float2bfloat16(v1.w));
        uint4 hi = make_uint4(pack_bf2(h0,h1), pack_bf2(h2,h3), pack_bf2(h4,h5), pack_bf2(h6,h7));
        uint4 lo = make_uint4(pack_bf2(v0.x-h0, v0.y-h1), pack_bf2(v0.z-h2, v0.w-h3),
                              pack_bf2(v1.x-h4, v1.y-h5), pack_bf2(v1.z-h6, v1.w-h7));
        uint32_t off = row * 256 + ((grp ^ (row & 7)) << 4);
        *(uint4*)(smem + SA_HI + off) = hi;
        *(uint4*)(smem + SA_LO + off) = lo;
    }
    // ---- stage B (pre-decomposed bf16, swizzled copies) ----
    #pragma unroll
    for (int i = 0; i < 8; i++) {
        int f   = tid + i * 256;
        int row = f >> 4;
        int kb  = f & 15;
        uint32_t off = row * 256 + ((kb ^ (row & 7)) << 4);
        *(uint4*)(smem + SB_HI + off) = *(const uint4*)(Bhi + (size_t)row * EDIM + kb * 8);
        *(uint4*)(smem + SB_LO + off) = *(const uint4*)(Blo + (size_t)row * EDIM + kb * 8);
    }
    __syncthreads();

    const int wm = wid & 1, wn = wid >> 1;
    const int m0 = wm * 64, n0 = wn * 32;

    // ldmatrix lane addressing: row = base + (lane&15), k-chunk += (lane>>4)
    const int lrow  = lane & 15;
    const int lkoff = lane >> 4;

    float acc[4][4][4];
    #pragma unroll
    for (int im = 0; im < 4; im++)
        #pragma unroll
        for (int in = 0; in < 4; in++)
            #pragma unroll
            for (int c = 0; c < 4; c++) acc[im][in][c] = 0.f;

    #pragma unroll
    for (int k16 = 0; k16 < 8; k16++) {
        const int kb = k16 * 2 + lkoff;
        uint32_t ah[4][4], al[4][4], bh[4][2], bl[4][2];
        #pragma unroll
        for (int im = 0; im < 4; im++) {
            int row = m0 + im * 16 + lrow;
            uint32_t off = row * 256 + ((kb ^ (row & 7)) << 4);
            ldsm4(ah[im], sb + SA_HI + off);
            ldsm4(al[im], sb + SA_LO + off);
        }
        #pragma unroll
        for (int p = 0; p < 2; p++) {
            int row = n0 + p * 16 + lrow;
            uint32_t off = row * 256 + ((kb ^ (row & 7)) << 4);
            uint32_t rh[4], rl[4];
            ldsm4(rh, sb + SB_HI + off);
            ldsm4(rl, sb + SB_LO + off);
            bh[2*p+0][0] = rh[0]; bh[2*p+0][1] = rh[2];
            bh[2*p+1][0] = rh[1]; bh[2*p+1][1] = rh[3];
            bl[2*p+0][0] = rl[0]; bl[2*p+0][1] = rl[2];
            bl[2*p+1][0] = rl[1]; bl[2*p+1][1] = rl[3];
        }
        #pragma unroll
        for (int im = 0; im < 4; im++)
            #pragma unroll
            for (int in = 0; in < 4; in++) {
                mma_bf16(acc[im][in], ah[im], bh[in]);
                mma_bf16(acc[im][in], ah[im], bl[in]);
                mma_bf16(acc[im][in], al[im], bh[in]);
            }
    }

    // ---- epilogue: direct register -> global ----
    const int gid = lane >> 2, tig = lane & 3;
    #pragma unroll
    for (int in = 0; in < 4; in++) {
        int col = n0 + in * 8 + tig * 2;
        float2 b2 = *(const float2*)(bias + col);
        #pragma unroll
        for (int im = 0; im < 4; im++) {
            #pragma unroll
            for (int rh = 0; rh < 2; rh++) {
                int row = m0 + im * 16 + gid + rh * 8;
                if (tile0 + row >= T) continue;
                float v0 = acc[im][in][rh * 2 + 0] + b2.x;
                float v1 = acc[im][in][rh * 2 + 1] + b2.y;
                if (RELU) { v0 = fmaxf(v0, 0.f); v1 = fmaxf(v1, 0.f); }
                float2 ov = make_float2(v0, v1);
                if (MODE == 0) {
                    *(float2*)(C + (size_t)(tile0 + row) * EDIM + col) = ov;
                } else if (MODE == 1) {
                    int h = col >> 5, ci = col & 31;
                    *(float2*)(C + ((size_t)h * T + tile0 + row) * HD + ci) = ov;
                } else {
                    int orow = dest[tile0 + row];
                    *(float2*)(C + (size_t)orow * EDIM + col) = ov;
                }
            }
        }
    }
}

// ---------------- attention: one block per (graph, head) ----------------
#define ATTN_SMEM (2 * LCAP * HD * 4)

__global__ __launch_bounds__(192)
void attn_kernel(const float* __restrict__ q, const float* __restrict__ k,
                 const float* __restrict__ v, float* __restrict__ ctx,
                 const int* __restrict__ off, int T)
{
    extern __shared__ float sm[];
    float* Ks = sm;
    float* Vs = sm + LCAP * HD;

    int g = blockIdx.x, h = blockIdx.y;
    int t0 = off[g] + g;
    int L  = off[g + 1] - off[g] + 1;
    int Ls = L < LCAP ? L : LCAP;
    int tid = threadIdx.x;

    const float* kh = k + (size_t)h * T * HD;
    const float* vh = v + (size_t)h * T * HD;
    const float* qh = q + (size_t)h * T * HD;

    for (int idx = tid; idx < Ls * 8; idx += blockDim.x) {
        *(float4*)(Ks + idx * 4) = *(const float4*)(kh + (size_t)t0 * HD + idx * 4);
        *(float4*)(Vs + idx * 4) = *(const float4*)(vh + (size_t)t0 * HD + idx * 4);
    }
    __syncthreads();

    const float scale = 0.17677669529663688f;

    for (int qi = tid; qi < L; qi += blockDim.x) {
        float qr[32];
        const float* qp = qh + (size_t)(t0 + qi) * HD;
        #pragma unroll
        for (int j4 = 0; j4 < 8; j4++) {
            float4 t4 = *(const float4*)(qp + j4 * 4);
            qr[j4 * 4 + 0] = t4.x * scale; qr[j4 * 4 + 1] = t4.y * scale;
            qr[j4 * 4 + 2] = t4.z * scale; qr[j4 * 4 + 3] = t4.w * scale;
        }
        float mx = -1e30f, s = 0.f;
        float acc[32];
        #pragma unroll
        for (int j = 0; j < 32; j++) acc[j] = 0.f;

        for (int mk = 0; mk < L; mk++) {
            const float* kp = (mk < Ls) ? (Ks + mk * HD) : (kh + (size_t)(t0 + mk) * HD);
            float d0 = 0.f, d1 = 0.f, d2 = 0.f, d3 = 0.f;
            #pragma unroll
            for (int j4 = 0; j4 < 8; j4++) {
                float4 k4 = *(const float4*)(kp + j4 * 4);
                d0 += qr[j4 * 4 + 0] * k4.x;
                d1 += qr[j4 * 4 + 1] * k4.y;
                d2 += qr[j4 * 4 + 2] * k4.z;
                d3 += qr[j4 * 4 + 3] * k4.w;
            }
            float xv = (d0 + d1) + (d2 + d3);
            float p;
            if (xv > mx) {                      // rare after first keys
                float c = __expf(mx - xv);
                s *= c;
                #pragma unroll
                for (int j = 0; j < 32; j++) acc[j] *= c;
                mx = xv;
                p = 1.f;
            } else {
                p = __expf(xv - mx);
            }
            s += p;
            const float* vp = (mk < Ls) ? (Vs + mk * HD) : (vh + (size_t)(t0 + mk) * HD);
            #pragma unroll
            for (int j4 = 0; j4 < 8; j4++) {
                float4 v4 = *(const float4*)(vp + j4 * 4);
                acc[j4 * 4 + 0] += p * v4.x;
                acc[j4 * 4 + 1] += p * v4.y;
                acc[j4 * 4 + 2] += p * v4.z;
                acc[j4 * 4 + 3] += p * v4.w;
            }
        }
        float inv = 1.f / s;
        float* cp = ctx + (size_t)(t0 + qi) * EDIM + h * HD;
        #pragma unroll
        for (int j4 = 0; j4 < 8; j4++) {
            *(float4*)(cp + j4 * 4) = make_float4(acc[j4*4+0]*inv, acc[j4*4+1]*inv,
                                                  acc[j4*4+2]*inv, acc[j4*4+3]*inv);
        }
    }
}

// ---------------- launch ----------------
extern "C" void kernel_launch(void* const* d_in, const int* in_sizes, int n_in,
                              void* d_out, int out_size)
{
    const float* x       = (const float*)d_in[0];
    const float* metal_x = (const float*)d_in[1];
    const int*   batch   = (const int*)  d_in[2];
    const float* Wk      = (const float*)d_in[3];
    const float* bk      = (const float*)d_in[4];
    const float* Wq      = (const float*)d_in[5];
    const float* bq      = (const float*)d_in[6];
    const float* in_w    = (const float*)d_in[7];
    const float* in_b    = (const float*)d_in[8];
    const float* out_w   = (const float*)d_in[9];
    const float* out_b   = (const float*)d_in[10];
    float* out = (float*)d_out;

    int N  = in_sizes[0] / EDIM;
    int nB = in_sizes[1] / EDIM;
    int T  = N + nB;

    float *value, *kin, *qin, *qb, *kb, *vb, *ctx;
    __nv_bfloat16 *wbhi, *wblo;
    int *off, *dest;
    cudaGetSymbolAddress((void**)&value, g_value);
    cudaGetSymbolAddress((void**)&kin,   g_kin);
    cudaGetSymbolAddress((void**)&qin,   g_qin);
    cudaGetSymbolAddress((void**)&qb,    g_q);
    cudaGetSymbolAddress((void**)&kb,    g_k);
    cudaGetSymbolAddress((void**)&vb,    g_v);
    cudaGetSymbolAddress((void**)&ctx,   g_ctx);
    cudaGetSymbolAddress((void**)&wbhi,  g_wbhi);
    cudaGetSymbolAddress((void**)&wblo,  g_wblo);
    cudaGetSymbolAddress((void**)&off,   g_off);
    cudaGetSymbolAddress((void**)&dest,  g_dest);

    cudaFuncSetAttribute(gemm_mma<1,0>, cudaFuncAttributeMaxDynamicSharedMemorySize, GEMM_SMEM);
    cudaFuncSetAttribute(gemm_mma<0,1>, cudaFuncAttributeMaxDynamicSharedMemorySize, GEMM_SMEM);
    cudaFuncSetAttribute(gemm_mma<0,2>, cudaFuncAttributeMaxDynamicSharedMemorySize, GEMM_SMEM);
    cudaFuncSetAttribute(attn_kernel,   cudaFuncAttributeMaxDynamicSharedMemorySize, ATTN_SMEM);

    const int W = EDIM * EDIM;
    offsets_kernel<<<(nB + 256) / 256, 256>>>(batch, N, nB, off);
    wdecomp_kernel<<<(6 * W + 255) / 256, 256>>>(Wk, Wq, in_w, out_w, wbhi, wblo);
    gather_kernel<<<(T + 7) / 8, 256>>>(x, metal_x, batch, off, N, nB, value, dest);

    int tiles = (T + 127) / 128;

    gemm_mma<1,0><<<tiles, 256, GEMM_SMEM>>>(value, wbhi,         wblo,         bk,          kin, nullptr, T);
    gemm_mma<1,0><<<tiles, 256, GEMM_SMEM>>>(value, wbhi + 1*W,   wblo + 1*W,   bq,          qin, nullptr, T);
    gemm_mma<0,1><<<tiles, 256, GEMM_SMEM>>>(qin,   wbhi + 2*W,   wblo + 2*W,   in_b,        qb,  nullptr, T);
    gemm_mma<0,1><<<tiles, 256, GEMM_SMEM>>>(kin,   wbhi + 3*W,   wblo + 3*W,   in_b + 128,  kb,  nullptr, T);
    gemm_mma<0,1><<<tiles, 256, GEMM_SMEM>>>(value, wbhi + 4*W,   wblo + 4*W,   in_b + 256,  vb,  nullptr, T);

    dim3 agrid(nB, NHEAD);
    attn_kernel<<<agrid, 192, ATTN_SMEM>>>(qb, kb, vb, ctx, off, T);

    gemm_mma<0,2><<<tiles, 256, GEMM_SMEM>>>(ctx, wbhi + 5*W, wblo + 5*W, out_b, out, dest, T);
}

// round 5
// speedup vs baseline: 1.8761x; 1.1741x over previous
#include <cuda_runtime.h>
#include <cuda_bf16.h>
#include <cstdint>

#define EDIM   128
#define NHEAD  4
#define HD     32
#define MAXN   65536
#define MAXB   512
#define MAXT   (MAXN + MAXB)
#define LCAP   192      // scalar-fallback smem staging cap
#define LP     192      // tensor attention max L (fallback beyond)

// ---------------- scratch ----------------
__device__ float g_value[(size_t)MAXT * EDIM];
__device__ float g_kin  [(size_t)MAXT * EDIM];
__device__ float g_qin  [(size_t)MAXT * EDIM];
__device__ float g_q    [(size_t)MAXT * EDIM];   // head-major [H][T][HD]
__device__ float g_k    [(size_t)MAXT * EDIM];
__device__ float g_v    [(size_t)MAXT * EDIM];
__device__ float g_ctx  [(size_t)MAXT * EDIM];
__device__ __nv_bfloat16 g_wbhi[6 * EDIM * EDIM];
__device__ __nv_bfloat16 g_wblo[6 * EDIM * EDIM];
__device__ int   g_off  [MAXB + 1];
__device__ int   g_dest [MAXT];

// ---------------- helpers ----------------
__device__ __forceinline__ uint32_t smem_u32(const void* p) {
    uint32_t a;
    asm("{ .reg .u64 t; cvta.to.shared.u64 t, %1; cvt.u32.u64 %0, t; }" : "=r"(a) : "l"(p));
    return a;
}
__device__ __forceinline__ void ldsm4(uint32_t* r, uint32_t addr) {
    asm volatile("ldmatrix.sync.aligned.m8n8.x4.shared.b16 {%0,%1,%2,%3}, [%4];"
                 : "=r"(r[0]), "=r"(r[1]), "=r"(r[2]), "=r"(r[3]) : "r"(addr));
}
__device__ __forceinline__ void mma_bf16(float* d, const uint32_t* a, const uint32_t* b) {
    asm volatile("mma.sync.aligned.m16n8k16.row.col.f32.bf16.bf16.f32 "
                 "{%0,%1,%2,%3}, {%4,%5,%6,%7}, {%8,%9}, {%0,%1,%2,%3};"
                 : "+f"(d[0]), "+f"(d[1]), "+f"(d[2]), "+f"(d[3])
                 : "r"(a[0]), "r"(a[1]), "r"(a[2]), "r"(a[3]), "r"(b[0]), "r"(b[1]));
}
__device__ __forceinline__ uint32_t pack_bf2(float a, float b) {
    __nv_bfloat162 t = __floats2bfloat162_rn(a, b);
    return *(uint32_t*)&t;
}
__device__ __forceinline__ float bf16_rt(float x) {   // round-trip through bf16
    return __bfloat162float(__float2bfloat16(x));
}

// ---------------- small setup kernels ----------------
__global__ void offsets_kernel(const int* __restrict__ batch, int N, int nB, int* __restrict__ off)
{
    int g = blockIdx.x * blockDim.x + threadIdx.x;
    if (g > nB) return;
    if (g == nB) { off[nB] = N; return; }
    int lo = 0, hi = N;
    while (lo < hi) { int m = (lo + hi) >> 1; if (batch[m] < g) lo = m + 1; else hi = m; }
    off[g] = lo;
}

__global__ void gather_kernel(const float* __restrict__ x, const float* __restrict__ mx,
                              const int* __restrict__ batch, const int* __restrict__ off,
                              int N, int nB, float* __restrict__ value, int* __restrict__ dest)
{
    int row  = blockIdx.x * 8 + (threadIdx.x >> 5);
    int lane = threadIdx.x & 31;
    if (row < N) {
        int g = batch[row]; int tok = row + g + 1;
        float4 v4 = *(const float4*)(x + (size_t)row * EDIM + lane * 4);
        *(float4*)(value + (size_t)tok * EDIM + lane * 4) = v4;
        if (lane == 0) dest[tok] = row;
    } else if (row < N + nB) {
        int g = row - N; int tok = off[g] + g;
        float4 v4 = *(const float4*)(mx + (size_t)g * EDIM + lane * 4);
        *(float4*)(value + (size_t)tok * EDIM + lane * 4) = v4;
        if (lane == 0) dest[tok] = N + g;
    }
}

__global__ void wdecomp_kernel(const float* __restrict__ Wk, const float* __restrict__ Wq,
                               const float* __restrict__ in_w, const float* __restrict__ out_w,
                               __nv_bfloat16* __restrict__ bhi, __nv_bfloat16* __restrict__ blo)
{
    int idx = blockIdx.x * 256 + threadIdx.x;
    if (idx >= 6 * EDIM * EDIM) return;
    int slab = idx >> 14, r = idx & 16383;
    float v = (slab == 0) ? Wk[r] : (slab == 1) ? Wq[r]
            : (slab < 5)  ? in_w[(size_t)(slab - 2) * EDIM * EDIM + r] : out_w[r];
    __nv_bfloat16 h = __float2bfloat16(v);
    bhi[idx] = h;
    blo[idx] = __float2bfloat16(v - __bfloat162float(h));
}

// ---------------- mma.sync GEMM (3xBF16), 128x128 tile ----------------
#define SA_HI 0
#define SA_LO 32768
#define SB_HI 65536
#define SB_LO 98304
#define GEMM_SMEM 131072

template<int RELU, int MODE>
__global__ __launch_bounds__(256, 1)
void gemm_mma(const float* __restrict__ A,
              const __nv_bfloat16* __restrict__ Bhi, const __nv_bfloat16* __restrict__ Blo,
              const float* __restrict__ bias, float* __restrict__ C,
              const int* __restrict__ dest, int T)
{
    extern __shared__ char smem[];
    const uint32_t sb = smem_u32(smem);
    const int tid  = threadIdx.x;
    const int wid  = tid >> 5, lane = tid & 31;
    const int tile0 = blockIdx.x * 128;

    #pragma unroll
    for (int i = 0; i < 8; i++) {
        int f   = tid + i * 256;
        int row = f >> 4;
        int grp = f & 15;
        float4 v0 = make_float4(0.f,0.f,0.f,0.f), v1 = v0;
        if (tile0 + row < T) {
            const float* p = A + (size_t)(tile0 + row) * EDIM + grp * 8;
            v0 = *(const float4*)p;
            v1 = *(const float4*)(p + 4);
        }
        float h0 = bf16_rt(v0.x), h1 = bf16_rt(v0.y), h2 = bf16_rt(v0.z), h3 = bf16_rt(v0.w);
        float h4 = bf16_rt(v1.x), h5 = bf16_rt(v1.y), h6 = bf16_rt(v1.z), h7 = bf16_rt(v1.w);
        uint4 hi = make_uint4(pack_bf2(h0,h1), pack_bf2(h2,h3), pack_bf2(h4,h5), pack_bf2(h6,h7));
        uint4 lo = make_uint4(pack_bf2(v0.x-h0, v0.y-h1), pack_bf2(v0.z-h2, v0.w-h3),
                              pack_bf2(v1.x-h4, v1.y-h5), pack_bf2(v1.z-h6, v1.w-h7));
        uint32_t off = row * 256 + ((grp ^ (row & 7)) << 4);
        *(uint4*)(smem + SA_HI + off) = hi;
        *(uint4*)(smem + SA_LO + off) = lo;
    }
    #pragma unroll
    for (int i = 0; i < 8; i++) {
        int f   = tid + i * 256;
        int row = f >> 4;
        int kb  = f & 15;
        uint32_t off = row * 256 + ((kb ^ (row & 7)) << 4);
        *(uint4*)(smem + SB_HI + off) = *(const uint4*)(Bhi + (size_t)row * EDIM + kb * 8);
        *(uint4*)(smem + SB_LO + off) = *(const uint4*)(Blo + (size_t)row * EDIM + kb * 8);
    }
    __syncthreads();

    const int wm = wid & 1, wn = wid >> 1;
    const int m0 = wm * 64, n0 = wn * 32;
    const int lrow  = lane & 15;
    const int lkoff = lane >> 4;

    float acc[4][4][4];
    #pragma unroll
    for (int im = 0; im < 4; im++)
        #pragma unroll
        for (int in = 0; in < 4; in++)
            #pragma unroll
            for (int c = 0; c < 4; c++) acc[im][in][c] = 0.f;

    #pragma unroll 1
    for (int k16 = 0; k16 < 8; k16++) {
        const int kb = k16 * 2 + lkoff;
        uint32_t ah[4][4], al[4][4], bh[4][2], bl[4][2];
        #pragma unroll
        for (int im = 0; im < 4; im++) {
            int row = m0 + im * 16 + lrow;
            uint32_t off = row * 256 + ((kb ^ (row & 7)) << 4);
            ldsm4(ah[im], sb + SA_HI + off);
            ldsm4(al[im], sb + SA_LO + off);
        }
        #pragma unroll
        for (int p = 0; p < 2; p++) {
            int row = n0 + p * 16 + lrow;
            uint32_t off = row * 256 + ((kb ^ (row & 7)) << 4);
            uint32_t rh[4], rl[4];
            ldsm4(rh, sb + SB_HI + off);
            ldsm4(rl, sb + SB_LO + off);
            bh[2*p+0][0] = rh[0]; bh[2*p+0][1] = rh[2];
            bh[2*p+1][0] = rh[1]; bh[2*p+1][1] = rh[3];
            bl[2*p+0][0] = rl[0]; bl[2*p+0][1] = rl[2];
            bl[2*p+1][0] = rl[1]; bl[2*p+1][1] = rl[3];
        }
        #pragma unroll
        for (int im = 0; im < 4; im++)
            #pragma unroll
            for (int in = 0; in < 4; in++) {
                mma_bf16(acc[im][in], ah[im], bh[in]);
                mma_bf16(acc[im][in], ah[im], bl[in]);
                mma_bf16(acc[im][in], al[im], bh[in]);
            }
    }

    const int gid = lane >> 2, tig = lane & 3;
    #pragma unroll
    for (int in = 0; in < 4; in++) {
        int col = n0 + in * 8 + tig * 2;
        float2 b2 = *(const float2*)(bias + col);
        #pragma unroll
        for (int im = 0; im < 4; im++) {
            #pragma unroll
            for (int rh = 0; rh < 2; rh++) {
                int row = m0 + im * 16 + gid + rh * 8;
                if (tile0 + row >= T) continue;
                float v0 = acc[im][in][rh * 2 + 0] + b2.x;
                float v1 = acc[im][in][rh * 2 + 1] + b2.y;
                if (RELU) { v0 = fmaxf(v0, 0.f); v1 = fmaxf(v1, 0.f); }
                float2 ov = make_float2(v0, v1);
                if (MODE == 0) {
                    *(float2*)(C + (size_t)(tile0 + row) * EDIM + col) = ov;
                } else if (MODE == 1) {
                    int h = col >> 5, ci = col & 31;
                    *(float2*)(C + ((size_t)h * T + tile0 + row) * HD + ci) = ov;
                } else {
                    int orow = dest[tile0 + row];
                    *(float2*)(C + (size_t)orow * EDIM + col) = ov;
                }
            }
        }
    }
}

// ---------------- tensor-core attention: one block per (graph, head) ----------------
// smem: Q/K hi,lo [LP][32] bf16 pitch 40 elems; V^T hi,lo [32][LP] pitch 200 elems
#define SQ_HI 0
#define SQ_LO 15360
#define SK_HI 30720
#define SK_LO 46080
#define SVT_HI 61440
#define SVT_LO 74240
#define ATTN_TC_SMEM 87040

__global__ __launch_bounds__(128, 2)
void attn_tc_kernel(const float* __restrict__ q, const float* __restrict__ k,
                    const float* __restrict__ v, float* __restrict__ ctx,
                    const int* __restrict__ off, int T)
{
    extern __shared__ char smem[];
    const uint32_t sb = smem_u32(smem);
    int g = blockIdx.x, h = blockIdx.y;
    int t0 = off[g] + g;
    int L  = off[g + 1] - off[g] + 1;
    if (L > LP) return;                      // scalar fallback handles

    const int tid = threadIdx.x;
    const float scale = 0.17677669529663688f;
    const float* qh_g = q + (size_t)h * T * HD;
    const float* kh_g = k + (size_t)h * T * HD;
    const float* vh_g = v + (size_t)h * T * HD;

    __nv_bfloat16* sQh = (__nv_bfloat16*)(smem + SQ_HI);
    __nv_bfloat16* sQl = (__nv_bfloat16*)(smem + SQ_LO);
    __nv_bfloat16* sKh = (__nv_bfloat16*)(smem + SK_HI);
    __nv_bfloat16* sKl = (__nv_bfloat16*)(smem + SK_LO);
    __nv_bfloat16* sVh = (__nv_bfloat16*)(smem + SVT_HI);
    __nv_bfloat16* sVl = (__nv_bfloat16*)(smem + SVT_LO);

    // stage tokens (zero pad rows)
    for (int m = tid; m < LP; m += 128) {
        if (m < L) {
            const float* qp = qh_g + (size_t)(t0 + m) * HD;
            const float* kp = kh_g + (size_t)(t0 + m) * HD;
            const float* vp = vh_g + (size_t)(t0 + m) * HD;
            #pragma unroll
            for (int d = 0; d < 32; d += 4) {
                float4 qv = *(const float4*)(qp + d);
                qv.x *= scale; qv.y *= scale; qv.z *= scale; qv.w *= scale;
                float4 kv = *(const float4*)(kp + d);
                float4 vv = *(const float4*)(vp + d);
                float qh0 = bf16_rt(qv.x), qh1 = bf16_rt(qv.y), qh2 = bf16_rt(qv.z), qh3 = bf16_rt(qv.w);
                float kh0 = bf16_rt(kv.x), kh1 = bf16_rt(kv.y), kh2 = bf16_rt(kv.z), kh3 = bf16_rt(kv.w);
                *(uint32_t*)(sQh + m * 40 + d)     = pack_bf2(qh0, qh1);
                *(uint32_t*)(sQh + m * 40 + d + 2) = pack_bf2(qh2, qh3);
                *(uint32_t*)(sQl + m * 40 + d)     = pack_bf2(qv.x - qh0, qv.y - qh1);
                *(uint32_t*)(sQl + m * 40 + d + 2) = pack_bf2(qv.z - qh2, qv.w - qh3);
                *(uint32_t*)(sKh + m * 40 + d)     = pack_bf2(kh0, kh1);
                *(uint32_t*)(sKh + m * 40 + d + 2) = pack_bf2(kh2, kh3);
                *(uint32_t*)(sKl + m * 40 + d)     = pack_bf2(kv.x - kh0, kv.y - kh1);
                *(uint32_t*)(sKl + m * 40 + d + 2) = pack_bf2(kv.z - kh2, kv.w - kh3);
                float vh0 = bf16_rt(vv.x), vh1 = bf16_rt(vv.y), vh2 = bf16_rt(vv.z), vh3 = bf16_rt(vv.w);
                sVh[(d+0)*200 + m] = __float2bfloat16(vh0);
                sVh[(d+1)*200 + m] = __float2bfloat16(vh1);
                sVh[(d+2)*200 + m] = __float2bfloat16(vh2);
                sVh[(d+3)*200 + m] = __float2bfloat16(vh3);
                sVl[(d+0)*200 + m] = __float2bfloat16(vv.x - vh0);
                sVl[(d+1)*200 + m] = __float2bfloat16(vv.y - vh1);
                sVl[(d+2)*200 + m] = __float2bfloat16(vv.z - vh2);
                sVl[(d+3)*200 + m] = __float2bfloat16(vv.w - vh3);
            }
        } else {
            #pragma unroll
            for (int d = 0; d < 32; d += 2) {
                *(uint32_t*)(sQh + m * 40 + d) = 0; *(uint32_t*)(sQl + m * 40 + d) = 0;
                *(uint32_t*)(sKh + m * 40 + d) = 0; *(uint32_t*)(sKl + m * 40 + d) = 0;
            }
            #pragma unroll
            for (int d = 0; d < 32; d++) {
                sVh[d*200 + m] = __float2bfloat16(0.f);
                sVl[d*200 + m] = __float2bfloat16(0.f);
            }
        }
    }
    __syncthreads();

    const int w = tid >> 5, lane = tid & 31;
    const int lr = lane & 15, lc = lane >> 4;
    const int ntAct  = (L + 7) >> 3;
    const int npairs = (ntAct + 1) >> 1;
    const int kAct   = (L + 15) >> 4;

    for (int m0 = w * 16; m0 < L; m0 += 64) {
        // Q fragments (2 k-steps of 16, hi/lo)
        uint32_t qfh[2][4], qfl[2][4];
        #pragma unroll
        for (int s = 0; s < 2; s++) {
            uint32_t a = sb + SQ_HI + (uint32_t)(m0 + lr) * 80 + s * 32 + lc * 16;
            ldsm4(qfh[s], a);
            ldsm4(qfl[s], a + (SQ_LO - SQ_HI));
        }
        // S = Q @ K^T
        float acc[24][4];
        #pragma unroll
        for (int t = 0; t < 24; t++) { acc[t][0]=0.f; acc[t][1]=0.f; acc[t][2]=0.f; acc[t][3]=0.f; }
        #pragma unroll 1
        for (int p = 0; p < 12; p++) {
            if (p >= npairs) break;
            #pragma unroll
            for (int s = 0; s < 2; s++) {
                uint32_t a = sb + SK_HI + (uint32_t)(p * 16 + lr) * 80 + s * 32 + lc * 16;
                uint32_t kh[4], kl[4];
                ldsm4(kh, a);
                ldsm4(kl, a + (SK_LO - SK_HI));
                uint32_t bh0[2] = {kh[0], kh[2]}, bh1[2] = {kh[1], kh[3]};
                uint32_t bl0[2] = {kl[0], kl[2]}, bl1[2] = {kl[1], kl[3]};
                mma_bf16(acc[2*p],   qfh[s], bh0);
                mma_bf16(acc[2*p],   qfh[s], bl0);
                mma_bf16(acc[2*p],   qfl[s], bh0);
                mma_bf16(acc[2*p+1], qfh[s], bh1);
                mma_bf16(acc[2*p+1], qfh[s], bl1);
                mma_bf16(acc[2*p+1], qfl[s], bh1);
            }
        }
        // softmax (full row in registers)
        float mx0 = -1e30f, mx1 = -1e30f;
        #pragma unroll
        for (int t = 0; t < 24; t++) {
            if (t >= ntAct) break;
            int c = t * 8 + ((lane & 3) << 1);
            if (c >= L)     { acc[t][0] = -1e30f; acc[t][2] = -1e30f; }
            if (c + 1 >= L) { acc[t][1] = -1e30f; acc[t][3] = -1e30f; }
            mx0 = fmaxf(mx0, fmaxf(acc[t][0], acc[t][1]));
            mx1 = fmaxf(mx1, fmaxf(acc[t][2], acc[t][3]));
        }
        mx0 = fmaxf(mx0, __shfl_xor_sync(0xffffffffu, mx0, 1));
        mx0 = fmaxf(mx0, __shfl_xor_sync(0xffffffffu, mx0, 2));
        mx1 = fmaxf(mx1, __shfl_xor_sync(0xffffffffu, mx1, 1));
        mx1 = fmaxf(mx1, __shfl_xor_sync(0xffffffffu, mx1, 2));
        float s0 = 0.f, s1 = 0.f;
        #pragma unroll
        for (int t = 0; t < 24; t++) {
            if (t >= ntAct) break;
            acc[t][0] = __expf(acc[t][0] - mx0);
            acc[t][1] = __expf(acc[t][1] - mx0);
            acc[t][2] = __expf(acc[t][2] - mx1);
            acc[t][3] = __expf(acc[t][3] - mx1);
            s0 += acc[t][0] + acc[t][1];
            s1 += acc[t][2] + acc[t][3];
        }
        s0 += __shfl_xor_sync(0xffffffffu, s0, 1);
        s0 += __shfl_xor_sync(0xffffffffu, s0, 2);
        s1 += __shfl_xor_sync(0xffffffffu, s1, 1);
        s1 += __shfl_xor_sync(0xffffffffu, s1, 2);
        float i0 = 1.f / s0, i1 = 1.f / s1;
        // pack P (normalized) into A fragments, hi/lo
        uint32_t pfh[12][4], pfl[12][4];
        #pragma unroll
        for (int kt = 0; kt < 12; kt++) {
            #pragma unroll
            for (int half = 0; half < 2; half++) {
                int t = 2 * kt + half;
                float p0 = 0.f, p1 = 0.f, p2 = 0.f, p3 = 0.f;
                if (t < ntAct) {
                    p0 = acc[t][0] * i0; p1 = acc[t][1] * i0;
                    p2 = acc[t][2] * i1; p3 = acc[t][3] * i1;
                }
                float h0 = bf16_rt(p0), h1 = bf16_rt(p1), h2 = bf16_rt(p2), h3 = bf16_rt(p3);
                pfh[kt][2*half + 0] = pack_bf2(h0, h1);
                pfh[kt][2*half + 1] = pack_bf2(h2, h3);
                pfl[kt][2*half + 0] = pack_bf2(p0 - h0, p1 - h1);
                pfl[kt][2*half + 1] = pack_bf2(p2 - h2, p3 - h3);
            }
        }
        // ctx = P @ V
        float cacc[4][4];
        #pragma unroll
        for (int n = 0; n < 4; n++) { cacc[n][0]=0.f; cacc[n][1]=0.f; cacc[n][2]=0.f; cacc[n][3]=0.f; }
        #pragma unroll 1
        for (int kt = 0; kt < 12; kt++) {
            if (kt >= kAct) break;
            #pragma unroll
            for (int n0 = 0; n0 < 2; n0++) {
                uint32_t a = sb + SVT_HI + (uint32_t)(n0 * 16 + lr) * 400 + kt * 32 + lc * 16;
                uint32_t vh[4], vl[4];
                ldsm4(vh, a);
                ldsm4(vl, a + (SVT_LO - SVT_HI));
                uint32_t bh0[2] = {vh[0], vh[2]}, bh1[2] = {vh[1], vh[3]};
                uint32_t bl0[2] = {vl[0], vl[2]}, bl1[2] = {vl[1], vl[3]};
                mma_bf16(cacc[2*n0],   pfh[kt], bh0);
                mma_bf16(cacc[2*n0],   pfh[kt], bl0);
                mma_bf16(cacc[2*n0],   pfl[kt], bh0);
                mma_bf16(cacc[2*n0+1], pfh[kt], bh1);
                mma_bf16(cacc[2*n0+1], pfh[kt], bl1);
                mma_bf16(cacc[2*n0+1], pfl[kt], bh1);
            }
        }
        // store
        int r0 = m0 + (lane >> 2), r1 = r0 + 8;
        #pragma unroll
        for (int nt = 0; nt < 4; nt++) {
            int col = nt * 8 + ((lane & 3) << 1);
            if (r0 < L)
                *(float2*)(ctx + (size_t)(t0 + r0) * EDIM + h * HD + col) =
                    make_float2(cacc[nt][0], cacc[nt][1]);
            if (r1 < L)
                *(float2*)(ctx + (size_t)(t0 + r1) * EDIM + h * HD + col) =
                    make_float2(cacc[nt][2], cacc[nt][3]);
        }
    }
}

// ---------------- scalar fallback attention (only L > LP blocks) ----------------
#define ATTN_SMEM (2 * LCAP * HD * 4)

__global__ __launch_bounds__(192)
void attn_kernel(const float* __restrict__ q, const float* __restrict__ k,
                 const float* __restrict__ v, float* __restrict__ ctx,
                 const int* __restrict__ off, int T)
{
    extern __shared__ float sm[];
    float* Ks = sm;
    float* Vs = sm + LCAP * HD;

    int g = blockIdx.x, h = blockIdx.y;
    int t0 = off[g] + g;
    int L  = off[g + 1] - off[g] + 1;
    if (L <= LP) return;                     // tensor kernel handled it
    int Ls = L < LCAP ? L : LCAP;
    int tid = threadIdx.x;

    const float* kh = k + (size_t)h * T * HD;
    const float* vh = v + (size_t)h * T * HD;
    const float* qh = q + (size_t)h * T * HD;

    for (int idx = tid; idx < Ls * 8; idx += blockDim.x) {
        *(float4*)(Ks + idx * 4) = *(const float4*)(kh + (size_t)t0 * HD + idx * 4);
        *(float4*)(Vs + idx * 4) = *(const float4*)(vh + (size_t)t0 * HD + idx * 4);
    }
    __syncthreads();

    const float scale = 0.17677669529663688f;
    for (int qi = tid; qi < L; qi += blockDim.x) {
        float qr[32];
        const float* qp = qh + (size_t)(t0 + qi) * HD;
        #pragma unroll
        for (int j4 = 0; j4 < 8; j4++) {
            float4 t4 = *(const float4*)(qp + j4 * 4);
            qr[j4*4+0] = t4.x * scale; qr[j4*4+1] = t4.y * scale;
            qr[j4*4+2] = t4.z * scale; qr[j4*4+3] = t4.w * scale;
        }
        float mx = -1e30f, s = 0.f;
        float acc[32];
        #pragma unroll
        for (int j = 0; j < 32; j++) acc[j] = 0.f;
        for (int mk = 0; mk < L; mk++) {
            const float* kp = (mk < Ls) ? (Ks + mk * HD) : (kh + (size_t)(t0 + mk) * HD);
            float d0 = 0.f, d1 = 0.f, d2 = 0.f, d3 = 0.f;
            #pragma unroll
            for (int j4 = 0; j4 < 8; j4++) {
                float4 k4 = *(const float4*)(kp + j4 * 4);
                d0 += qr[j4*4+0] * k4.x; d1 += qr[j4*4+1] * k4.y;
                d2 += qr[j4*4+2] * k4.z; d3 += qr[j4*4+3] * k4.w;
            }
            float xv = (d0 + d1) + (d2 + d3);
            float p;
            if (xv > mx) {
                float c = __expf(mx - xv);
                s *= c;
                #pragma unroll
                for (int j = 0; j < 32; j++) acc[j] *= c;
                mx = xv; p = 1.f;
            } else p = __expf(xv - mx);
            s += p;
            const float* vp = (mk < Ls) ? (Vs + mk * HD) : (vh + (size_t)(t0 + mk) * HD);
            #pragma unroll
            for (int j4 = 0; j4 < 8; j4++) {
                float4 v4 = *(const float4*)(vp + j4 * 4);
                acc[j4*4+0] += p * v4.x; acc[j4*4+1] += p * v4.y;
                acc[j4*4+2] += p * v4.z; acc[j4*4+3] += p * v4.w;
            }
        }
        float inv = 1.f / s;
        float* cp = ctx + (size_t)(t0 + qi) * EDIM + h * HD;
        #pragma unroll
        for (int j4 = 0; j4 < 8; j4++)
            *(float4*)(cp + j4 * 4) = make_float4(acc[j4*4+0]*inv, acc[j4*4+1]*inv,
                                                  acc[j4*4+2]*inv, acc[j4*4+3]*inv);
    }
}

// ---------------- launch ----------------
extern "C" void kernel_launch(void* const* d_in, const int* in_sizes, int n_in,
                              void* d_out, int out_size)
{
    const float* x       = (const float*)d_in[0];
    const float* metal_x = (const float*)d_in[1];
    const int*   batch   = (const int*)  d_in[2];
    const float* Wk      = (const float*)d_in[3];
    const float* bk      = (const float*)d_in[4];
    const float* Wq      = (const float*)d_in[5];
    const float* bq      = (const float*)d_in[6];
    const float* in_w    = (const float*)d_in[7];
    const float* in_b    = (const float*)d_in[8];
    const float* out_w   = (const float*)d_in[9];
    const float* out_b   = (const float*)d_in[10];
    float* out = (float*)d_out;

    int N  = in_sizes[0] / EDIM;
    int nB = in_sizes[1] / EDIM;
    int T  = N + nB;

    float *value, *kin, *qin, *qb, *kb, *vb, *ctx;
    __nv_bfloat16 *wbhi, *wblo;
    int *off, *dest;
    cudaGetSymbolAddress((void**)&value, g_value);
    cudaGetSymbolAddress((void**)&kin,   g_kin);
    cudaGetSymbolAddress((void**)&qin,   g_qin);
    cudaGetSymbolAddress((void**)&qb,    g_q);
    cudaGetSymbolAddress((void**)&kb,    g_k);
    cudaGetSymbolAddress((void**)&vb,    g_v);
    cudaGetSymbolAddress((void**)&ctx,   g_ctx);
    cudaGetSymbolAddress((void**)&wbhi,  g_wbhi);
    cudaGetSymbolAddress((void**)&wblo,  g_wblo);
    cudaGetSymbolAddress((void**)&off,   g_off);
    cudaGetSymbolAddress((void**)&dest,  g_dest);

    cudaFuncSetAttribute(gemm_mma<1,0>,  cudaFuncAttributeMaxDynamicSharedMemorySize, GEMM_SMEM);
    cudaFuncSetAttribute(gemm_mma<0,1>,  cudaFuncAttributeMaxDynamicSharedMemorySize, GEMM_SMEM);
    cudaFuncSetAttribute(gemm_mma<0,2>,  cudaFuncAttributeMaxDynamicSharedMemorySize, GEMM_SMEM);
    cudaFuncSetAttribute(attn_tc_kernel, cudaFuncAttributeMaxDynamicSharedMemorySize, ATTN_TC_SMEM);
    cudaFuncSetAttribute(attn_kernel,    cudaFuncAttributeMaxDynamicSharedMemorySize, ATTN_SMEM);

    const int W = EDIM * EDIM;
    offsets_kernel<<<(nB + 256) / 256, 256>>>(batch, N, nB, off);
    wdecomp_kernel<<<(6 * W + 255) / 256, 256>>>(Wk, Wq, in_w, out_w, wbhi, wblo);
    gather_kernel<<<(T + 7) / 8, 256>>>(x, metal_x, batch, off, N, nB, value, dest);

    int tiles = (T + 127) / 128;

    gemm_mma<1,0><<<tiles, 256, GEMM_SMEM>>>(value, wbhi,       wblo,       bk,         kin, nullptr, T);
    gemm_mma<1,0><<<tiles, 256, GEMM_SMEM>>>(value, wbhi + 1*W, wblo + 1*W, bq,         qin, nullptr, T);
    gemm_mma<0,1><<<tiles, 256, GEMM_SMEM>>>(qin,   wbhi + 2*W, wblo + 2*W, in_b,       qb,  nullptr, T);
    gemm_mma<0,1><<<tiles, 256, GEMM_SMEM>>>(kin,   wbhi + 3*W, wblo + 3*W, in_b + 128, kb,  nullptr, T);
    gemm_mma<0,1><<<tiles, 256, GEMM_SMEM>>>(value, wbhi + 4*W, wblo + 4*W, in_b + 256, vb,  nullptr, T);

    dim3 agrid(nB, NHEAD);
    attn_tc_kernel<<<agrid, 128, ATTN_TC_SMEM>>>(qb, kb, vb, ctx, off, T);
    attn_kernel<<<agrid, 192, ATTN_SMEM>>>(qb, kb, vb, ctx, off, T);

    gemm_mma<0,2><<<tiles, 256, GEMM_SMEM>>>(ctx, wbhi + 5*W, wblo + 5*W, out_b, out, dest, T);
}

// round 6
// speedup vs baseline: 2.0991x; 1.1189x over previous
#include <cuda_runtime.h>
#include <cuda_bf16.h>
#include <cstdint>

#define EDIM   128
#define NHEAD  4
#define HD     32
#define MAXN   65536
#define MAXB   512
#define MAXT   (MAXN + MAXB)
#define LCAP   256      // scalar-fallback smem staging cap
#define LP     192      // tensor attention max L

// ---------------- scratch ----------------
__device__ float g_value[(size_t)MAXT * EDIM];
__device__ float g_kin  [(size_t)MAXT * EDIM];
__device__ float g_qin  [(size_t)MAXT * EDIM];
__device__ float g_q    [(size_t)MAXT * EDIM];   // head-major [H][T][HD]
__device__ float g_k    [(size_t)MAXT * EDIM];
__device__ float g_v    [(size_t)MAXT * EDIM];
__device__ float g_ctx  [(size_t)MAXT * EDIM];
__device__ __nv_bfloat16 g_wbhi[6 * EDIM * EDIM];
__device__ __nv_bfloat16 g_wblo[6 * EDIM * EDIM];
__device__ int   g_off  [MAXB + 1];
__device__ int   g_dest [MAXT];

// ---------------- helpers ----------------
__device__ __forceinline__ uint32_t smem_u32(const void* p) {
    uint32_t a;
    asm("{ .reg .u64 t; cvta.to.shared.u64 t, %1; cvt.u32.u64 %0, t; }" : "=r"(a) : "l"(p));
    return a;
}
__device__ __forceinline__ void ldsm4(uint32_t* r, uint32_t addr) {
    asm volatile("ldmatrix.sync.aligned.m8n8.x4.shared.b16 {%0,%1,%2,%3}, [%4];"
                 : "=r"(r[0]), "=r"(r[1]), "=r"(r[2]), "=r"(r[3]) : "r"(addr));
}
__device__ __forceinline__ void ldsm4t(uint32_t* r, uint32_t addr) {
    asm volatile("ldmatrix.sync.aligned.m8n8.x4.trans.shared.b16 {%0,%1,%2,%3}, [%4];"
                 : "=r"(r[0]), "=r"(r[1]), "=r"(r[2]), "=r"(r[3]) : "r"(addr));
}
__device__ __forceinline__ void mma_bf16(float* d, const uint32_t* a, const uint32_t* b) {
    asm volatile("mma.sync.aligned.m16n8k16.row.col.f32.bf16.bf16.f32 "
                 "{%0,%1,%2,%3}, {%4,%5,%6,%7}, {%8,%9}, {%0,%1,%2,%3};"
                 : "+f"(d[0]), "+f"(d[1]), "+f"(d[2]), "+f"(d[3])
                 : "r"(a[0]), "r"(a[1]), "r"(a[2]), "r"(a[3]), "r"(b[0]), "r"(b[1]));
}
__device__ __forceinline__ uint32_t pack_bf2(float a, float b) {
    __nv_bfloat162 t = __floats2bfloat162_rn(a, b);
    return *(uint32_t*)&t;
}
__device__ __forceinline__ float bf16_rt(float x) {
    return __bfloat162float(__float2bfloat16(x));
}

// ---------------- small setup kernels ----------------
__global__ void offsets_kernel(const int* __restrict__ batch, int N, int nB, int* __restrict__ off)
{
    int g = blockIdx.x * blockDim.x + threadIdx.x;
    if (g > nB) return;
    if (g == nB) { off[nB] = N; return; }
    int lo = 0, hi = N;
    while (lo < hi) { int m = (lo + hi) >> 1; if (batch[m] < g) lo = m + 1; else hi = m; }
    off[g] = lo;
}

__global__ void gather_kernel(const float* __restrict__ x, const float* __restrict__ mx,
                              const int* __restrict__ batch, const int* __restrict__ off,
                              int N, int nB, float* __restrict__ value, int* __restrict__ dest)
{
    int row  = blockIdx.x * 8 + (threadIdx.x >> 5);
    int lane = threadIdx.x & 31;
    if (row < N) {
        int g = batch[row]; int tok = row + g + 1;
        float4 v4 = *(const float4*)(x + (size_t)row * EDIM + lane * 4);
        *(float4*)(value + (size_t)tok * EDIM + lane * 4) = v4;
        if (lane == 0) dest[tok] = row;
    } else if (row < N + nB) {
        int g = row - N; int tok = off[g] + g;
        float4 v4 = *(const float4*)(mx + (size_t)g * EDIM + lane * 4);
        *(float4*)(value + (size_t)tok * EDIM + lane * 4) = v4;
        if (lane == 0) dest[tok] = N + g;
    }
}

__global__ void wdecomp_kernel(const float* __restrict__ Wk, const float* __restrict__ Wq,
                               const float* __restrict__ in_w, const float* __restrict__ out_w,
                               __nv_bfloat16* __restrict__ bhi, __nv_bfloat16* __restrict__ blo)
{
    int idx = blockIdx.x * 256 + threadIdx.x;
    if (idx >= 6 * EDIM * EDIM) return;
    int slab = idx >> 14, r = idx & 16383;
    float v = (slab == 0) ? Wk[r] : (slab == 1) ? Wq[r]
            : (slab < 5)  ? in_w[(size_t)(slab - 2) * EDIM * EDIM + r] : out_w[r];
    __nv_bfloat16 h = __float2bfloat16(v);
    bhi[idx] = h;
    blo[idx] = __float2bfloat16(v - __bfloat162float(h));
}

// ================= mma.sync GEMM core, 64x128 tile =================
// smem: A hi/lo 2x16KB, B hi/lo 2x32KB = 96KB -> 2 CTAs/SM.
#define GA_HI 0
#define GA_LO 16384
#define GB_HI 32768
#define GB_LO 65536
#define GEMM_SMEM 98304

// stage A rows [tile0, tile0+64) into smem hi/lo (swizzled)
__device__ __forceinline__ void stage_A64(const float* __restrict__ A, int tile0, int T,
                                          char* smem, int tid)
{
    #pragma unroll
    for (int i = 0; i < 4; i++) {
        int f   = tid + i * 256;          // 0..1023
        int row = f >> 4;
        int grp = f & 15;
        float4 v0 = make_float4(0.f,0.f,0.f,0.f), v1 = v0;
        if (tile0 + row < T) {
            const float* p = A + (size_t)(tile0 + row) * EDIM + grp * 8;
            v0 = *(const float4*)p;
            v1 = *(const float4*)(p + 4);
        }
        float h0 = bf16_rt(v0.x), h1 = bf16_rt(v0.y), h2 = bf16_rt(v0.z), h3 = bf16_rt(v0.w);
        float h4 = bf16_rt(v1.x), h5 = bf16_rt(v1.y), h6 = bf16_rt(v1.z), h7 = bf16_rt(v1.w);
        uint4 hi = make_uint4(pack_bf2(h0,h1), pack_bf2(h2,h3), pack_bf2(h4,h5), pack_bf2(h6,h7));
        uint4 lo = make_uint4(pack_bf2(v0.x-h0, v0.y-h1), pack_bf2(v0.z-h2, v0.w-h3),
                              pack_bf2(v1.x-h4, v1.y-h5), pack_bf2(v1.z-h6, v1.w-h7));
        uint32_t off = row * 256 + ((grp ^ (row & 7)) << 4);
        *(uint4*)(smem + GA_HI + off) = hi;
        *(uint4*)(smem + GA_LO + off) = lo;
    }
}

__device__ __forceinline__ void stage_B(const __nv_bfloat16* __restrict__ Bhi,
                                        const __nv_bfloat16* __restrict__ Blo,
                                        char* smem, int tid)
{
    #pragma unroll
    for (int i = 0; i < 8; i++) {
        int f   = tid + i * 256;
        int row = f >> 4;
        int kb  = f & 15;
        uint32_t off = row * 256 + ((kb ^ (row & 7)) << 4);
        *(uint4*)(smem + GB_HI + off) = *(const uint4*)(Bhi + (size_t)row * EDIM + kb * 8);
        *(uint4*)(smem + GB_LO + off) = *(const uint4*)(Blo + (size_t)row * EDIM + kb * 8);
    }
}

// compute 64x128 tile + epilogue. MODE: 0 token-major, 1 head-major, 2 dest scatter.
template<int RELU, int MODE>
__device__ __forceinline__ void gemm_tile(uint32_t sb, const float* __restrict__ bias,
                                          float* __restrict__ C, const int* __restrict__ dest,
                                          int tile0, int T, int wid, int lane)
{
    const int wm = wid & 1, wn = wid >> 1;
    const int m0 = wm * 32, n0 = wn * 32;
    const int lrow  = lane & 15;
    const int lkoff = lane >> 4;

    float acc[2][4][4];
    #pragma unroll
    for (int im = 0; im < 2; im++)
        #pragma unroll
        for (int in = 0; in < 4; in++)
            #pragma unroll
            for (int c = 0; c < 4; c++) acc[im][in][c] = 0.f;

    #pragma unroll 1
    for (int k16 = 0; k16 < 8; k16++) {
        const int kb = k16 * 2 + lkoff;
        uint32_t ah[2][4], al[2][4], bh[4][2], bl[4][2];
        #pragma unroll
        for (int im = 0; im < 2; im++) {
            int row = m0 + im * 16 + lrow;
            uint32_t off = row * 256 + ((kb ^ (row & 7)) << 4);
            ldsm4(ah[im], sb + GA_HI + off);
            ldsm4(al[im], sb + GA_LO + off);
        }
        #pragma unroll
        for (int p = 0; p < 2; p++) {
            int row = n0 + p * 16 + lrow;
            uint32_t off = row * 256 + ((kb ^ (row & 7)) << 4);
            uint32_t rh[4], rl[4];
            ldsm4(rh, sb + GB_HI + off);
            ldsm4(rl, sb + GB_LO + off);
            bh[2*p+0][0] = rh[0]; bh[2*p+0][1] = rh[2];
            bh[2*p+1][0] = rh[1]; bh[2*p+1][1] = rh[3];
            bl[2*p+0][0] = rl[0]; bl[2*p+0][1] = rl[2];
            bl[2*p+1][0] = rl[1]; bl[2*p+1][1] = rl[3];
        }
        #pragma unroll
        for (int im = 0; im < 2; im++)
            #pragma unroll
            for (int in = 0; in < 4; in++) {
                mma_bf16(acc[im][in], ah[im], bh[in]);
                mma_bf16(acc[im][in], ah[im], bl[in]);
                mma_bf16(acc[im][in], al[im], bh[in]);
            }
    }

    const int gid = lane >> 2, tig = lane & 3;
    #pragma unroll
    for (int in = 0; in < 4; in++) {
        int col = n0 + in * 8 + tig * 2;
        float2 b2 = *(const float2*)(bias + col);
        #pragma unroll
        for (int im = 0; im < 2; im++) {
            #pragma unroll
            for (int rh = 0; rh < 2; rh++) {
                int row = m0 + im * 16 + gid + rh * 8;
                if (tile0 + row >= T) continue;
                float v0 = acc[im][in][rh * 2 + 0] + b2.x;
                float v1 = acc[im][in][rh * 2 + 1] + b2.y;
                if (RELU) { v0 = fmaxf(v0, 0.f); v1 = fmaxf(v1, 0.f); }
                float2 ov = make_float2(v0, v1);
                if (MODE == 0) {
                    *(float2*)(C + (size_t)(tile0 + row) * EDIM + col) = ov;
                } else if (MODE == 1) {
                    int h = col >> 5, ci = col & 31;
                    *(float2*)(C + ((size_t)h * T + tile0 + row) * HD + ci) = ov;
                } else {
                    int orow = dest[tile0 + row];
                    *(float2*)(C + (size_t)orow * EDIM + col) = ov;
                }
            }
        }
    }
}

// single-output GEMM
template<int RELU, int MODE>
__global__ __launch_bounds__(256, 2)
void gemm_single(const float* __restrict__ A,
                 const __nv_bfloat16* __restrict__ Bhi, const __nv_bfloat16* __restrict__ Blo,
                 const float* __restrict__ bias, float* __restrict__ C,
                 const int* __restrict__ dest, int T)
{
    extern __shared__ char smem[];
    const uint32_t sb = smem_u32(smem);
    const int tid = threadIdx.x, wid = tid >> 5, lane = tid & 31;
    const int tile0 = blockIdx.x * 64;
    stage_A64(A, tile0, T, smem, tid);
    stage_B(Bhi, Blo, smem, tid);
    __syncthreads();
    gemm_tile<RELU, MODE>(sb, bias, C, dest, tile0, T, wid, lane);
}

// fused 3-output GEMM: A=value -> kin(relu), qin(relu), vb(head-major)
__global__ __launch_bounds__(256, 2)
void gemm_fused3(const float* __restrict__ A,
                 const __nv_bfloat16* __restrict__ Bh0, const __nv_bfloat16* __restrict__ Bl0,
                 const __nv_bfloat16* __restrict__ Bh1, const __nv_bfloat16* __restrict__ Bl1,
                 const __nv_bfloat16* __restrict__ Bh2, const __nv_bfloat16* __restrict__ Bl2,
                 const float* __restrict__ bias0, const float* __restrict__ bias1,
                 const float* __restrict__ bias2,
                 float* __restrict__ C0, float* __restrict__ C1, float* __restrict__ C2,
                 int T)
{
    extern __shared__ char smem[];
    const uint32_t sb = smem_u32(smem);
    const int tid = threadIdx.x, wid = tid >> 5, lane = tid & 31;
    const int tile0 = blockIdx.x * 64;

    stage_A64(A, tile0, T, smem, tid);

    stage_B(Bh0, Bl0, smem, tid);
    __syncthreads();
    gemm_tile<1,0>(sb, bias0, C0, nullptr, tile0, T, wid, lane);
    __syncthreads();

    stage_B(Bh1, Bl1, smem, tid);
    __syncthreads();
    gemm_tile<1,0>(sb, bias1, C1, nullptr, tile0, T, wid, lane);
    __syncthreads();

    stage_B(Bh2, Bl2, smem, tid);
    __syncthreads();
    gemm_tile<0,1>(sb, bias2, C2, nullptr, tile0, T, wid, lane);
}

// ================= tensor-core attention =================
// smem: Q,K,V hi/lo, each [LP][32] bf16 pitch 40 elems (80B) = 15360B; total 92160B.
#define SQ_HI 0
#define SQ_LO 15360
#define SK_HI 30720
#define SK_LO 46080
#define SV_HI 61440
#define SV_LO 76800
#define ATTN_TC_SMEM 92160

__global__ __launch_bounds__(128, 2)
void attn_tc_kernel(const float* __restrict__ q, const float* __restrict__ k,
                    const float* __restrict__ v, float* __restrict__ ctx,
                    const int* __restrict__ off, int T)
{
    extern __shared__ char smem[];
    const uint32_t sb = smem_u32(smem);
    int g = blockIdx.x, h = blockIdx.y;
    int t0 = off[g] + g;
    int L  = off[g + 1] - off[g] + 1;
    if (L > LP) return;                      // scalar fallback handles
    int Lpad = (L + 15) & ~15;

    const int tid = threadIdx.x;
    const float scale = 0.17677669529663688f;
    const float* qh_g = q + (size_t)h * T * HD;
    const float* kh_g = k + (size_t)h * T * HD;
    const float* vh_g = v + (size_t)h * T * HD;

    __nv_bfloat16* sQh = (__nv_bfloat16*)(smem + SQ_HI);
    __nv_bfloat16* sQl = (__nv_bfloat16*)(smem + SQ_LO);
    __nv_bfloat16* sKh = (__nv_bfloat16*)(smem + SK_HI);
    __nv_bfloat16* sKl = (__nv_bfloat16*)(smem + SK_LO);
    __nv_bfloat16* sVh = (__nv_bfloat16*)(smem + SV_HI);
    __nv_bfloat16* sVl = (__nv_bfloat16*)(smem + SV_LO);

    for (int m = tid; m < Lpad; m += 128) {
        if (m < L) {
            const float* qp = qh_g + (size_t)(t0 + m) * HD;
            const float* kp = kh_g + (size_t)(t0 + m) * HD;
            const float* vp = vh_g + (size_t)(t0 + m) * HD;
            #pragma unroll
            for (int d = 0; d < 32; d += 4) {
                float4 qv = *(const float4*)(qp + d);
                qv.x *= scale; qv.y *= scale; qv.z *= scale; qv.w *= scale;
                float4 kv = *(const float4*)(kp + d);
                float4 vv = *(const float4*)(vp + d);
                float q0 = bf16_rt(qv.x), q1 = bf16_rt(qv.y), q2 = bf16_rt(qv.z), q3 = bf16_rt(qv.w);
                float k0 = bf16_rt(kv.x), k1 = bf16_rt(kv.y), k2 = bf16_rt(kv.z), k3 = bf16_rt(kv.w);
                float v0 = bf16_rt(vv.x), v1 = bf16_rt(vv.y), v2 = bf16_rt(vv.z), v3 = bf16_rt(vv.w);
                *(uint32_t*)(sQh + m * 40 + d)     = pack_bf2(q0, q1);
                *(uint32_t*)(sQh + m * 40 + d + 2) = pack_bf2(q2, q3);
                *(uint32_t*)(sQl + m * 40 + d)     = pack_bf2(qv.x - q0, qv.y - q1);
                *(uint32_t*)(sQl + m * 40 + d + 2) = pack_bf2(qv.z - q2, qv.w - q3);
                *(uint32_t*)(sKh + m * 40 + d)     = pack_bf2(k0, k1);
                *(uint32_t*)(sKh + m * 40 + d + 2) = pack_bf2(k2, k3);
                *(uint32_t*)(sKl + m * 40 + d)     = pack_bf2(kv.x - k0, kv.y - k1);
                *(uint32_t*)(sKl + m * 40 + d + 2) = pack_bf2(kv.z - k2, kv.w - k3);
                *(uint32_t*)(sVh + m * 40 + d)     = pack_bf2(v0, v1);
                *(uint32_t*)(sVh + m * 40 + d + 2) = pack_bf2(v2, v3);
                *(uint32_t*)(sVl + m * 40 + d)     = pack_bf2(vv.x - v0, vv.y - v1);
                *(uint32_t*)(sVl + m * 40 + d + 2) = pack_bf2(vv.z - v2, vv.w - v3);
            }
        } else {
            #pragma unroll
            for (int d = 0; d < 32; d += 2) {
                *(uint32_t*)(sQh + m * 40 + d) = 0; *(uint32_t*)(sQl + m * 40 + d) = 0;
                *(uint32_t*)(sKh + m * 40 + d) = 0; *(uint32_t*)(sKl + m * 40 + d) = 0;
                *(uint32_t*)(sVh + m * 40 + d) = 0; *(uint32_t*)(sVl + m * 40 + d) = 0;
            }
        }
    }
    __syncthreads();

    const int w = tid >> 5, lane = tid & 31;
    const int lr = lane & 15, lc = lane >> 4;
    const int ntAct  = (L + 7) >> 3;
    const int npairs = (ntAct + 1) >> 1;
    const int kAct   = (L + 15) >> 4;

    for (int m0 = w * 16; m0 < L; m0 += 64) {
        uint32_t qfh[2][4], qfl[2][4];
        #pragma unroll
        for (int s = 0; s < 2; s++) {
            uint32_t a = sb + SQ_HI + (uint32_t)(m0 + lr) * 80 + s * 32 + lc * 16;
            ldsm4(qfh[s], a);
            ldsm4(qfl[s], a + (SQ_LO - SQ_HI));
        }
        // S = Q @ K^T
        float acc[24][4];
        #pragma unroll
        for (int t = 0; t < 24; t++) { acc[t][0]=0.f; acc[t][1]=0.f; acc[t][2]=0.f; acc[t][3]=0.f; }
        #pragma unroll 1
        for (int p = 0; p < 12; p++) {
            if (p >= npairs) break;
            #pragma unroll
            for (int s = 0; s < 2; s++) {
                uint32_t a = sb + SK_HI + (uint32_t)(p * 16 + lr) * 80 + s * 32 + lc * 16;
                uint32_t kh[4], kl[4];
                ldsm4(kh, a);
                ldsm4(kl, a + (SK_LO - SK_HI));
                uint32_t bh0[2] = {kh[0], kh[2]}, bh1[2] = {kh[1], kh[3]};
                uint32_t bl0[2] = {kl[0], kl[2]}, bl1[2] = {kl[1], kl[3]};
                mma_bf16(acc[2*p],   qfh[s], bh0);
                mma_bf16(acc[2*p],   qfh[s], bl0);
                mma_bf16(acc[2*p],   qfl[s], bh0);
                mma_bf16(acc[2*p+1], qfh[s], bh1);
                mma_bf16(acc[2*p+1], qfh[s], bl1);
                mma_bf16(acc[2*p+1], qfl[s], bh1);
            }
        }
        // softmax
        float mx0 = -1e30f, mx1 = -1e30f;
        #pragma unroll
        for (int t = 0; t < 24; t++) {
            if (t >= ntAct) break;
            int c = t * 8 + ((lane & 3) << 1);
            if (c >= L)     { acc[t][0] = -1e30f; acc[t][2] = -1e30f; }
            if (c + 1 >= L) { acc[t][1] = -1e30f; acc[t][3] = -1e30f; }
            mx0 = fmaxf(mx0, fmaxf(acc[t][0], acc[t][1]));
            mx1 = fmaxf(mx1, fmaxf(acc[t][2], acc[t][3]));
        }
        mx0 = fmaxf(mx0, __shfl_xor_sync(0xffffffffu, mx0, 1));
        mx0 = fmaxf(mx0, __shfl_xor_sync(0xffffffffu, mx0, 2));
        mx1 = fmaxf(mx1, __shfl_xor_sync(0xffffffffu, mx1, 1));
        mx1 = fmaxf(mx1, __shfl_xor_sync(0xffffffffu, mx1, 2));
        float s0 = 0.f, s1 = 0.f;
        #pragma unroll
        for (int t = 0; t < 24; t++) {
            if (t >= ntAct) break;
            acc[t][0] = __expf(acc[t][0] - mx0);
            acc[t][1] = __expf(acc[t][1] - mx0);
            acc[t][2] = __expf(acc[t][2] - mx1);
            acc[t][3] = __expf(acc[t][3] - mx1);
            s0 += acc[t][0] + acc[t][1];
            s1 += acc[t][2] + acc[t][3];
        }
        s0 += __shfl_xor_sync(0xffffffffu, s0, 1);
        s0 += __shfl_xor_sync(0xffffffffu, s0, 2);
        s1 += __shfl_xor_sync(0xffffffffu, s1, 1);
        s1 += __shfl_xor_sync(0xffffffffu, s1, 2);
        float i0 = 1.f / s0, i1 = 1.f / s1;
        // P fragments (normalized, hi/lo)
        uint32_t pfh[12][4], pfl[12][4];
        #pragma unroll
        for (int kt = 0; kt < 12; kt++) {
            #pragma unroll
            for (int half = 0; half < 2; half++) {
                int t = 2 * kt + half;
                float p0 = 0.f, p1 = 0.f, p2 = 0.f, p3 = 0.f;
                if (t < ntAct) {
                    p0 = acc[t][0] * i0; p1 = acc[t][1] * i0;
                    p2 = acc[t][2] * i1; p3 = acc[t][3] * i1;
                }
                float h0 = bf16_rt(p0), h1 = bf16_rt(p1), h2 = bf16_rt(p2), h3 = bf16_rt(p3);
                pfh[kt][2*half + 0] = pack_bf2(h0, h1);
                pfh[kt][2*half + 1] = pack_bf2(h2, h3);
                pfl[kt][2*half + 0] = pack_bf2(p0 - h0, p1 - h1);
                pfl[kt][2*half + 1] = pack_bf2(p2 - h2, p3 - h3);
            }
        }
        // ctx = P @ V  (V row-major, B frags via ldmatrix.trans)
        float cacc[4][4];
        #pragma unroll
        for (int n = 0; n < 4; n++) { cacc[n][0]=0.f; cacc[n][1]=0.f; cacc[n][2]=0.f; cacc[n][3]=0.f; }
        // lane addressing for x4.trans: mat = lane>>3 (0..3); row k = kt*16 + (mat&1)*8 + (lane&7); col n = n0 + (mat>>1)*8
        const uint32_t vrow = ((lane >> 3) & 1) * 8 + (lane & 7);
        const uint32_t vcol = (lane >> 4) * 8;
        #pragma unroll 1
        for (int kt = 0; kt < 12; kt++) {
            if (kt >= kAct) break;
            #pragma unroll
            for (int ng = 0; ng < 2; ng++) {      // n0 = ng*16
                uint32_t a = sb + SV_HI + (uint32_t)(kt * 16 + vrow) * 80 + (ng * 16 + vcol) * 2;
                uint32_t vh[4], vl[4];
                ldsm4t(vh, a);
                ldsm4t(vl, a + (SV_LO - SV_HI));
                uint32_t bh0[2] = {vh[0], vh[1]}, bh1[2] = {vh[2], vh[3]};
                uint32_t bl0[2] = {vl[0], vl[1]}, bl1[2] = {vl[2], vl[3]};
                mma_bf16(cacc[2*ng],   pfh[kt], bh0);
                mma_bf16(cacc[2*ng],   pfh[kt], bl0);
                mma_bf16(cacc[2*ng],   pfl[kt], bh0);
                mma_bf16(cacc[2*ng+1], pfh[kt], bh1);
                mma_bf16(cacc[2*ng+1], pfh[kt], bl1);
                mma_bf16(cacc[2*ng+1], pfl[kt], bh1);
            }
        }
        // store
        int r0 = m0 + (lane >> 2), r1 = r0 + 8;
        #pragma unroll
        for (int nt = 0; nt < 4; nt++) {
            int col = nt * 8 + ((lane & 3) << 1);
            if (r0 < L)
                *(float2*)(ctx + (size_t)(t0 + r0) * EDIM + h * HD + col) =
                    make_float2(cacc[nt][0], cacc[nt][1]);
            if (r1 < L)
                *(float2*)(ctx + (size_t)(t0 + r1) * EDIM + h * HD + col) =
                    make_float2(cacc[nt][2], cacc[nt][3]);
        }
    }
}

// ---------------- scalar fallback attention (only L > LP) ----------------
#define ATTN_SMEM (2 * LCAP * HD * 4)

__global__ __launch_bounds__(192)
void attn_kernel(const float* __restrict__ q, const float* __restrict__ k,
                 const float* __restrict__ v, float* __restrict__ ctx,
                 const int* __restrict__ off, int T)
{
    extern __shared__ float sm[];
    float* Ks = sm;
    float* Vs = sm + LCAP * HD;

    int g = blockIdx.x, h = blockIdx.y;
    int t0 = off[g] + g;
    int L  = off[g + 1] - off[g] + 1;
    if (L <= LP) return;
    int Ls = L < LCAP ? L : LCAP;
    int tid = threadIdx.x;

    const float* kh = k + (size_t)h * T * HD;
    const float* vh = v + (size_t)h * T * HD;
    const float* qh = q + (size_t)h * T * HD;

    for (int idx = tid; idx < Ls * 8; idx += blockDim.x) {
        *(float4*)(Ks + idx * 4) = *(const float4*)(kh + (size_t)t0 * HD + idx * 4);
        *(float4*)(Vs + idx * 4) = *(const float4*)(vh + (size_t)t0 * HD + idx * 4);
    }
    __syncthreads();

    const float scale = 0.17677669529663688f;
    for (int qi = tid; qi < L; qi += blockDim.x) {
        float qr[32];
        const float* qp = qh + (size_t)(t0 + qi) * HD;
        #pragma unroll
        for (int j4 = 0; j4 < 8; j4++) {
            float4 t4 = *(const float4*)(qp + j4 * 4);
            qr[j4*4+0] = t4.x * scale; qr[j4*4+1] = t4.y * scale;
            qr[j4*4+2] = t4.z * scale; qr[j4*4+3] = t4.w * scale;
        }
        float mx = -1e30f, s = 0.f;
        float acc[32];
        #pragma unroll
        for (int j = 0; j < 32; j++) acc[j] = 0.f;
        for (int mk = 0; mk < L; mk++) {
            const float* kp = (mk < Ls) ? (Ks + mk * HD) : (kh + (size_t)(t0 + mk) * HD);
            float d0 = 0.f, d1 = 0.f, d2 = 0.f, d3 = 0.f;
            #pragma unroll
            for (int j4 = 0; j4 < 8; j4++) {
                float4 k4 = *(const float4*)(kp + j4 * 4);
                d0 += qr[j4*4+0] * k4.x; d1 += qr[j4*4+1] * k4.y;
                d2 += qr[j4*4+2] * k4.z; d3 += qr[j4*4+3] * k4.w;
            }
            float xv = (d0 + d1) + (d2 + d3);
            float p;
            if (xv > mx) {
                float c = __expf(mx - xv);
                s *= c;
                #pragma unroll
                for (int j = 0; j < 32; j++) acc[j] *= c;
                mx = xv; p = 1.f;
            } else p = __expf(xv - mx);
            s += p;
            const float* vp = (mk < Ls) ? (Vs + mk * HD) : (vh + (size_t)(t0 + mk) * HD);
            #pragma unroll
            for (int j4 = 0; j4 < 8; j4++) {
                float4 v4 = *(const float4*)(vp + j4 * 4);
                acc[j4*4+0] += p * v4.x; acc[j4*4+1] += p * v4.y;
                acc[j4*4+2] += p * v4.z; acc[j4*4+3] += p * v4.w;
            }
        }
        float inv = 1.f / s;
        float* cp = ctx + (size_t)(t0 + qi) * EDIM + h * HD;
        #pragma unroll
        for (int j4 = 0; j4 < 8; j4++)
            *(float4*)(cp + j4 * 4) = make_float4(acc[j4*4+0]*inv, acc[j4*4+1]*inv,
                                                  acc[j4*4+2]*inv, acc[j4*4+3]*inv);
    }
}

// ---------------- launch ----------------
extern "C" void kernel_launch(void* const* d_in, const int* in_sizes, int n_in,
                              void* d_out, int out_size)
{
    const float* x       = (const float*)d_in[0];
    const float* metal_x = (const float*)d_in[1];
    const int*   batch   = (const int*)  d_in[2];
    const float* Wk      = (const float*)d_in[3];
    const float* bk      = (const float*)d_in[4];
    const float* Wq      = (const float*)d_in[5];
    const float* bq      = (const float*)d_in[6];
    const float* in_w    = (const float*)d_in[7];
    const float* in_b    = (const float*)d_in[8];
    const float* out_w   = (const float*)d_in[9];
    const float* out_b   = (const float*)d_in[10];
    float* out = (float*)d_out;

    int N  = in_sizes[0] / EDIM;
    int nB = in_sizes[1] / EDIM;
    int T  = N + nB;

    float *value, *kin, *qin, *qb, *kb, *vb, *ctx;
    __nv_bfloat16 *wbhi, *wblo;
    int *off, *dest;
    cudaGetSymbolAddress((void**)&value, g_value);
    cudaGetSymbolAddress((void**)&kin,   g_kin);
    cudaGetSymbolAddress((void**)&qin,   g_qin);
    cudaGetSymbolAddress((void**)&qb,    g_q);
    cudaGetSymbolAddress((void**)&kb,    g_k);
    cudaGetSymbolAddress((void**)&vb,    g_v);
    cudaGetSymbolAddress((void**)&ctx,   g_ctx);
    cudaGetSymbolAddress((void**)&wbhi,  g_wbhi);
    cudaGetSymbolAddress((void**)&wblo,  g_wblo);
    cudaGetSymbolAddress((void**)&off,   g_off);
    cudaGetSymbolAddress((void**)&dest,  g_dest);

    cudaFuncSetAttribute(gemm_fused3,     cudaFuncAttributeMaxDynamicSharedMemorySize, GEMM_SMEM);
    cudaFuncSetAttribute(gemm_single<0,1>, cudaFuncAttributeMaxDynamicSharedMemorySize, GEMM_SMEM);
    cudaFuncSetAttribute(gemm_single<0,2>, cudaFuncAttributeMaxDynamicSharedMemorySize, GEMM_SMEM);
    cudaFuncSetAttribute(attn_tc_kernel,  cudaFuncAttributeMaxDynamicSharedMemorySize, ATTN_TC_SMEM);
    cudaFuncSetAttribute(attn_kernel,     cudaFuncAttributeMaxDynamicSharedMemorySize, ATTN_SMEM);

    const int W = EDIM * EDIM;
    offsets_kernel<<<(nB + 256) / 256, 256>>>(batch, N, nB, off);
    wdecomp_kernel<<<(6 * W + 255) / 256, 256>>>(Wk, Wq, in_w, out_w, wbhi, wblo);
    gather_kernel<<<(T + 7) / 8, 256>>>(x, metal_x, batch, off, N, nB, value, dest);

    int tiles = (T + 63) / 64;

    // value -> kin(relu), qin(relu), vb(head-major)
    gemm_fused3<<<tiles, 256, GEMM_SMEM>>>(value,
        wbhi,       wblo,        // Wk
        wbhi + 1*W, wblo + 1*W,  // Wq
        wbhi + 4*W, wblo + 4*W,  // in_v
        bk, bq, in_b + 256,
        kin, qin, vb, T);

    // qin -> qb, kin -> kb (head-major)
    gemm_single<0,1><<<tiles, 256, GEMM_SMEM>>>(qin, wbhi + 2*W, wblo + 2*W, in_b,       qb, nullptr, T);
    gemm_single<0,1><<<tiles, 256, GEMM_SMEM>>>(kin, wbhi + 3*W, wblo + 3*W, in_b + 128, kb, nullptr, T);

    dim3 agrid(nB, NHEAD);
    attn_tc_kernel<<<agrid, 128, ATTN_TC_SMEM>>>(qb, kb, vb, ctx, off, T);
    attn_kernel<<<agrid, 192, ATTN_SMEM>>>(qb, kb, vb, ctx, off, T);

    // ctx -> out (dest scatter)
    gemm_single<0,2><<<tiles, 256, GEMM_SMEM>>>(ctx, wbhi + 5*W, wblo + 5*W, out_b, out, dest, T);
}

// round 7
// speedup vs baseline: 2.3399x; 1.1147x over previous
#include <cuda_runtime.h>
#include <cuda_bf16.h>
#include <cstdint>

#define EDIM   128
#define NHEAD  4
#define HD     32
#define MAXN   65536
#define MAXB   512
#define MAXT   (MAXN + MAXB)
#define LCAP   256      // scalar-fallback smem staging cap
#define LP     160      // tensor attention max L (fallback beyond)

// ---------------- scratch (all intermediates decomposed bf16 hi/lo) ----------------
__device__ float g_value[(size_t)MAXT * EDIM];
__device__ __nv_bfloat16 g_kinh[(size_t)MAXT * EDIM];
__device__ __nv_bfloat16 g_kinl[(size_t)MAXT * EDIM];
__device__ __nv_bfloat16 g_qinh[(size_t)MAXT * EDIM];
__device__ __nv_bfloat16 g_qinl[(size_t)MAXT * EDIM];
__device__ __nv_bfloat16 g_qbh [(size_t)MAXT * EDIM];   // head-major [H][T][32], scaled
__device__ __nv_bfloat16 g_qbl [(size_t)MAXT * EDIM];
__device__ __nv_bfloat16 g_kbh [(size_t)MAXT * EDIM];
__device__ __nv_bfloat16 g_kbl [(size_t)MAXT * EDIM];
__device__ __nv_bfloat16 g_vbh [(size_t)MAXT * EDIM];
__device__ __nv_bfloat16 g_vbl [(size_t)MAXT * EDIM];
__device__ __nv_bfloat16 g_ctxh[(size_t)MAXT * EDIM];   // token-major [T][128]
__device__ __nv_bfloat16 g_ctxl[(size_t)MAXT * EDIM];
__device__ __nv_bfloat16 g_wbhi[6 * EDIM * EDIM];
__device__ __nv_bfloat16 g_wblo[6 * EDIM * EDIM];
__device__ int   g_off  [MAXB + 1];
__device__ int   g_dest [MAXT];

// ---------------- helpers ----------------
__device__ __forceinline__ uint32_t smem_u32(const void* p) {
    uint32_t a;
    asm("{ .reg .u64 t; cvta.to.shared.u64 t, %1; cvt.u32.u64 %0, t; }" : "=r"(a) : "l"(p));
    return a;
}
__device__ __forceinline__ void ldsm4(uint32_t* r, uint32_t addr) {
    asm volatile("ldmatrix.sync.aligned.m8n8.x4.shared.b16 {%0,%1,%2,%3}, [%4];"
                 : "=r"(r[0]), "=r"(r[1]), "=r"(r[2]), "=r"(r[3]) : "r"(addr));
}
__device__ __forceinline__ void ldsm4t(uint32_t* r, uint32_t addr) {
    asm volatile("ldmatrix.sync.aligned.m8n8.x4.trans.shared.b16 {%0,%1,%2,%3}, [%4];"
                 : "=r"(r[0]), "=r"(r[1]), "=r"(r[2]), "=r"(r[3]) : "r"(addr));
}
__device__ __forceinline__ void mma_bf16(float* d, const uint32_t* a, const uint32_t* b) {
    asm volatile("mma.sync.aligned.m16n8k16.row.col.f32.bf16.bf16.f32 "
                 "{%0,%1,%2,%3}, {%4,%5,%6,%7}, {%8,%9}, {%0,%1,%2,%3};"
                 : "+f"(d[0]), "+f"(d[1]), "+f"(d[2]), "+f"(d[3])
                 : "r"(a[0]), "r"(a[1]), "r"(a[2]), "r"(a[3]), "r"(b[0]), "r"(b[1]));
}
__device__ __forceinline__ uint32_t pack_bf2(float a, float b) {
    __nv_bfloat162 t = __floats2bfloat162_rn(a, b);
    return *(uint32_t*)&t;
}
__device__ __forceinline__ float bf16_rt(float x) {
    return __bfloat162float(__float2bfloat16(x));
}

// ---------------- small setup kernels ----------------
__global__ void offsets_kernel(const int* __restrict__ batch, int N, int nB, int* __restrict__ off)
{
    int g = blockIdx.x * blockDim.x + threadIdx.x;
    if (g > nB) return;
    if (g == nB) { off[nB] = N; return; }
    int lo = 0, hi = N;
    while (lo < hi) { int m = (lo + hi) >> 1; if (batch[m] < g) lo = m + 1; else hi = m; }
    off[g] = lo;
}

__global__ void gather_kernel(const float* __restrict__ x, const float* __restrict__ mx,
                              const int* __restrict__ batch, const int* __restrict__ off,
                              int N, int nB, float* __restrict__ value, int* __restrict__ dest)
{
    int row  = blockIdx.x * 8 + (threadIdx.x >> 5);
    int lane = threadIdx.x & 31;
    if (row < N) {
        int g = batch[row]; int tok = row + g + 1;
        float4 v4 = *(const float4*)(x + (size_t)row * EDIM + lane * 4);
        *(float4*)(value + (size_t)tok * EDIM + lane * 4) = v4;
        if (lane == 0) dest[tok] = row;
    } else if (row < N + nB) {
        int g = row - N; int tok = off[g] + g;
        float4 v4 = *(const float4*)(mx + (size_t)g * EDIM + lane * 4);
        *(float4*)(value + (size_t)tok * EDIM + lane * 4) = v4;
        if (lane == 0) dest[tok] = N + g;
    }
}

__global__ void wdecomp_kernel(const float* __restrict__ Wk, const float* __restrict__ Wq,
                               const float* __restrict__ in_w, const float* __restrict__ out_w,
                               __nv_bfloat16* __restrict__ bhi, __nv_bfloat16* __restrict__ blo)
{
    int idx = blockIdx.x * 256 + threadIdx.x;
    if (idx >= 6 * EDIM * EDIM) return;
    int slab = idx >> 14, r = idx & 16383;
    float v = (slab == 0) ? Wk[r] : (slab == 1) ? Wq[r]
            : (slab < 5)  ? in_w[(size_t)(slab - 2) * EDIM * EDIM + r] : out_w[r];
    __nv_bfloat16 h = __float2bfloat16(v);
    bhi[idx] = h;
    blo[idx] = __float2bfloat16(v - __bfloat162float(h));
}

// ================= GEMM core, 64x128 tile, 96KB smem -> 2 CTAs/SM =================
#define GA_HI 0
#define GA_LO 16384
#define GB_HI 32768
#define GB_LO 65536
#define GEMM_SMEM 98304

// stage A from fp32 (decompose)
__device__ __forceinline__ void stage_A_f32(const float* __restrict__ A, int tile0, int T,
                                            char* smem, int tid)
{
    #pragma unroll
    for (int i = 0; i < 4; i++) {
        int f   = tid + i * 256;
        int row = f >> 4;
        int grp = f & 15;
        float4 v0 = make_float4(0.f,0.f,0.f,0.f), v1 = v0;
        if (tile0 + row < T) {
            const float* p = A + (size_t)(tile0 + row) * EDIM + grp * 8;
            v0 = *(const float4*)p;
            v1 = *(const float4*)(p + 4);
        }
        float h0 = bf16_rt(v0.x), h1 = bf16_rt(v0.y), h2 = bf16_rt(v0.z), h3 = bf16_rt(v0.w);
        float h4 = bf16_rt(v1.x), h5 = bf16_rt(v1.y), h6 = bf16_rt(v1.z), h7 = bf16_rt(v1.w);
        uint4 hi = make_uint4(pack_bf2(h0,h1), pack_bf2(h2,h3), pack_bf2(h4,h5), pack_bf2(h6,h7));
        uint4 lo = make_uint4(pack_bf2(v0.x-h0, v0.y-h1), pack_bf2(v0.z-h2, v0.w-h3),
                              pack_bf2(v1.x-h4, v1.y-h5), pack_bf2(v1.z-h6, v1.w-h7));
        uint32_t off = row * 256 + ((grp ^ (row & 7)) << 4);
        *(uint4*)(smem + GA_HI + off) = hi;
        *(uint4*)(smem + GA_LO + off) = lo;
    }
}

// stage A from pre-decomposed token-major bf16 hi/lo (pure copy)
__device__ __forceinline__ void stage_A_pre(const __nv_bfloat16* __restrict__ Ah,
                                            const __nv_bfloat16* __restrict__ Al,
                                            int tile0, int T, char* smem, int tid)
{
    #pragma unroll
    for (int i = 0; i < 4; i++) {
        int f   = tid + i * 256;
        int row = f >> 4;
        int grp = f & 15;
        uint4 hi = make_uint4(0,0,0,0), lo = hi;
        if (tile0 + row < T) {
            hi = *(const uint4*)(Ah + (size_t)(tile0 + row) * EDIM + grp * 8);
            lo = *(const uint4*)(Al + (size_t)(tile0 + row) * EDIM + grp * 8);
        }
        uint32_t off = row * 256 + ((grp ^ (row & 7)) << 4);
        *(uint4*)(smem + GA_HI + off) = hi;
        *(uint4*)(smem + GA_LO + off) = lo;
    }
}

__device__ __forceinline__ void stage_B(const __nv_bfloat16* __restrict__ Bhi,
                                        const __nv_bfloat16* __restrict__ Blo,
                                        char* smem, int tid)
{
    #pragma unroll
    for (int i = 0; i < 8; i++) {
        int f   = tid + i * 256;
        int row = f >> 4;
        int kb  = f & 15;
        uint32_t off = row * 256 + ((kb ^ (row & 7)) << 4);
        *(uint4*)(smem + GB_HI + off) = *(const uint4*)(Bhi + (size_t)row * EDIM + kb * 8);
        *(uint4*)(smem + GB_LO + off) = *(const uint4*)(Blo + (size_t)row * EDIM + kb * 8);
    }
}

// 3xBF16 compute: acc[2][4][4] per warp (tile 32x32 at (wm*32, wn*32))
__device__ __forceinline__ void compute_frags(uint32_t sb, float acc[2][4][4], int wid, int lane)
{
    const int wm = wid & 1, wn = wid >> 1;
    const int m0 = wm * 32, n0 = wn * 32;
    const int lrow  = lane & 15;
    const int lkoff = lane >> 4;

    #pragma unroll
    for (int im = 0; im < 2; im++)
        #pragma unroll
        for (int in = 0; in < 4; in++)
            #pragma unroll
            for (int c = 0; c < 4; c++) acc[im][in][c] = 0.f;

    #pragma unroll 1
    for (int k16 = 0; k16 < 8; k16++) {
        const int kb = k16 * 2 + lkoff;
        uint32_t ah[2][4], al[2][4], bh[4][2], bl[4][2];
        #pragma unroll
        for (int im = 0; im < 2; im++) {
            int row = m0 + im * 16 + lrow;
            uint32_t off = row * 256 + ((kb ^ (row & 7)) << 4);
            ldsm4(ah[im], sb + GA_HI + off);
            ldsm4(al[im], sb + GA_LO + off);
        }
        #pragma unroll
        for (int p = 0; p < 2; p++) {
            int row = n0 + p * 16 + lrow;
            uint32_t off = row * 256 + ((kb ^ (row & 7)) << 4);
            uint32_t rh[4], rl[4];
            ldsm4(rh, sb + GB_HI + off);
            ldsm4(rl, sb + GB_LO + off);
            bh[2*p+0][0] = rh[0]; bh[2*p+0][1] = rh[2];
            bh[2*p+1][0] = rh[1]; bh[2*p+1][1] = rh[3];
            bl[2*p+0][0] = rl[0]; bl[2*p+0][1] = rl[2];
            bl[2*p+1][0] = rl[1]; bl[2*p+1][1] = rl[3];
        }
        #pragma unroll
        for (int im = 0; im < 2; im++)
            #pragma unroll
            for (int in = 0; in < 4; in++) {
                mma_bf16(acc[im][in], ah[im], bh[in]);
                mma_bf16(acc[im][in], ah[im], bl[in]);
                mma_bf16(acc[im][in], al[im], bh[in]);
            }
    }
}

// epilogue: decomposed token-major (relu always; for kin/qin)
__device__ __forceinline__ void epi_tok_decomp(const float acc[2][4][4], const float* __restrict__ bias,
                                               __nv_bfloat16* __restrict__ Xh, __nv_bfloat16* __restrict__ Xl,
                                               int tile0, int T, int wid, int lane)
{
    const int wm = wid & 1, wn = wid >> 1;
    const int m0 = wm * 32, n0 = wn * 32;
    const int gid = lane >> 2, tig = lane & 3;
    #pragma unroll
    for (int in = 0; in < 4; in++) {
        int col = n0 + in * 8 + tig * 2;
        float2 b2 = *(const float2*)(bias + col);
        #pragma unroll
        for (int im = 0; im < 2; im++)
            #pragma unroll
            for (int rh = 0; rh < 2; rh++) {
                int row = m0 + im * 16 + gid + rh * 8;
                if (tile0 + row >= T) continue;
                float v0 = fmaxf(acc[im][in][rh*2+0] + b2.x, 0.f);
                float v1 = fmaxf(acc[im][in][rh*2+1] + b2.y, 0.f);
                float h0 = bf16_rt(v0), h1 = bf16_rt(v1);
                size_t o = (size_t)(tile0 + row) * EDIM + col;
                *(uint32_t*)(Xh + o) = pack_bf2(h0, h1);
                *(uint32_t*)(Xl + o) = pack_bf2(v0 - h0, v1 - h1);
            }
    }
}

// epilogue: decomposed head-major [H][T][32], optional scale
__device__ __forceinline__ void epi_head_decomp(const float acc[2][4][4], const float* __restrict__ bias,
                                                __nv_bfloat16* __restrict__ Ch, __nv_bfloat16* __restrict__ Cl,
                                                int tile0, int T, float scale, int wid, int lane)
{
    const int wm = wid & 1, wn = wid >> 1;
    const int m0 = wm * 32, n0 = wn * 32;
    const int gid = lane >> 2, tig = lane & 3;
    #pragma unroll
    for (int in = 0; in < 4; in++) {
        int col = n0 + in * 8 + tig * 2;
        float2 b2 = *(const float2*)(bias + col);
        int hh = col >> 5, ci = col & 31;
        #pragma unroll
        for (int im = 0; im < 2; im++)
            #pragma unroll
            for (int rh = 0; rh < 2; rh++) {
                int row = m0 + im * 16 + gid + rh * 8;
                if (tile0 + row >= T) continue;
                float v0 = (acc[im][in][rh*2+0] + b2.x) * scale;
                float v1 = (acc[im][in][rh*2+1] + b2.y) * scale;
                float h0 = bf16_rt(v0), h1 = bf16_rt(v1);
                size_t o = ((size_t)hh * T + tile0 + row) * HD + ci;
                *(uint32_t*)(Ch + o) = pack_bf2(h0, h1);
                *(uint32_t*)(Cl + o) = pack_bf2(v0 - h0, v1 - h1);
            }
    }
}

// fused: value -> kin(decomp), qin(decomp), v(head-major decomp)
__global__ __launch_bounds__(256, 2)
void gemm_fused3(const float* __restrict__ A,
                 const __nv_bfloat16* __restrict__ Wk_h, const __nv_bfloat16* __restrict__ Wk_l,
                 const __nv_bfloat16* __restrict__ Wq_h, const __nv_bfloat16* __restrict__ Wq_l,
                 const __nv_bfloat16* __restrict__ Wv_h, const __nv_bfloat16* __restrict__ Wv_l,
                 const float* __restrict__ bk, const float* __restrict__ bq, const float* __restrict__ bv,
                 __nv_bfloat16* kinh, __nv_bfloat16* kinl,
                 __nv_bfloat16* qinh, __nv_bfloat16* qinl,
                 __nv_bfloat16* vbh,  __nv_bfloat16* vbl, int T)
{
    extern __shared__ char smem[];
    const uint32_t sb = smem_u32(smem);
    const int tid = threadIdx.x, wid = tid >> 5, lane = tid & 31;
    const int tile0 = blockIdx.x * 64;
    float acc[2][4][4];

    stage_A_f32(A, tile0, T, smem, tid);

    stage_B(Wk_h, Wk_l, smem, tid);
    __syncthreads();
    compute_frags(sb, acc, wid, lane);
    epi_tok_decomp(acc, bk, kinh, kinl, tile0, T, wid, lane);
    __syncthreads();

    stage_B(Wq_h, Wq_l, smem, tid);
    __syncthreads();
    compute_frags(sb, acc, wid, lane);
    epi_tok_decomp(acc, bq, qinh, qinl, tile0, T, wid, lane);
    __syncthreads();

    stage_B(Wv_h, Wv_l, smem, tid);
    __syncthreads();
    compute_frags(sb, acc, wid, lane);
    epi_head_decomp(acc, bv, vbh, vbl, tile0, T, 1.f, wid, lane);
}

// pre-decomposed A -> head-major decomposed output (qb/kb)
__global__ __launch_bounds__(256, 2)
void gemm_singleH(const __nv_bfloat16* __restrict__ Ah, const __nv_bfloat16* __restrict__ Al,
                  const __nv_bfloat16* __restrict__ Bhi, const __nv_bfloat16* __restrict__ Blo,
                  const float* __restrict__ bias,
                  __nv_bfloat16* __restrict__ Ch, __nv_bfloat16* __restrict__ Cl,
                  int T, float scale)
{
    extern __shared__ char smem[];
    const uint32_t sb = smem_u32(smem);
    const int tid = threadIdx.x, wid = tid >> 5, lane = tid & 31;
    const int tile0 = blockIdx.x * 64;
    stage_A_pre(Ah, Al, tile0, T, smem, tid);
    stage_B(Bhi, Blo, smem, tid);
    __syncthreads();
    float acc[2][4][4];
    compute_frags(sb, acc, wid, lane);
    epi_head_decomp(acc, bias, Ch, Cl, tile0, T, scale, wid, lane);
}

// pre-decomposed A (ctx) -> fp32 output with dest scatter (out proj)
__global__ __launch_bounds__(256, 2)
void gemm_singleOut(const __nv_bfloat16* __restrict__ Ah, const __nv_bfloat16* __restrict__ Al,
                    const __nv_bfloat16* __restrict__ Bhi, const __nv_bfloat16* __restrict__ Blo,
                    const float* __restrict__ bias, float* __restrict__ C,
                    const int* __restrict__ dest, int T)
{
    extern __shared__ char smem[];
    const uint32_t sb = smem_u32(smem);
    const int tid = threadIdx.x, wid = tid >> 5, lane = tid & 31;
    const int tile0 = blockIdx.x * 64;
    stage_A_pre(Ah, Al, tile0, T, smem, tid);
    stage_B(Bhi, Blo, smem, tid);
    __syncthreads();
    float acc[2][4][4];
    compute_frags(sb, acc, wid, lane);

    const int wm = wid & 1, wn = wid >> 1;
    const int m0 = wm * 32, n0 = wn * 32;
    const int gid = lane >> 2, tig = lane & 3;
    #pragma unroll
    for (int in = 0; in < 4; in++) {
        int col = n0 + in * 8 + tig * 2;
        float2 b2 = *(const float2*)(bias + col);
        #pragma unroll
        for (int im = 0; im < 2; im++)
            #pragma unroll
            for (int rh = 0; rh < 2; rh++) {
                int row = m0 + im * 16 + gid + rh * 8;
                if (tile0 + row >= T) continue;
                int orow = dest[tile0 + row];
                *(float2*)(C + (size_t)orow * EDIM + col) =
                    make_float2(acc[im][in][rh*2+0] + b2.x, acc[im][in][rh*2+1] + b2.y);
            }
    }
}

// ================= tensor-core attention: 256 threads, copy staging =================
// smem: Q,K,V hi/lo, each [LP][32] bf16 pitch 40 elems (80B) = 12800B; total 76800B.
#define SQ_HI 0
#define SQ_LO 12800
#define SK_HI 25600
#define SK_LO 38400
#define SV_HI 51200
#define SV_LO 64000
#define ATTN_TC_SMEM 76800

__global__ __launch_bounds__(256, 2)
void attn_tc_kernel(const __nv_bfloat16* __restrict__ qbh, const __nv_bfloat16* __restrict__ qbl,
                    const __nv_bfloat16* __restrict__ kbh, const __nv_bfloat16* __restrict__ kbl,
                    const __nv_bfloat16* __restrict__ vbh, const __nv_bfloat16* __restrict__ vbl,
                    __nv_bfloat16* __restrict__ ctxh, __nv_bfloat16* __restrict__ ctxl,
                    const int* __restrict__ off, int T)
{
    extern __shared__ char smem[];
    const uint32_t sb = smem_u32(smem);
    int g = blockIdx.x, h = blockIdx.y;
    int t0 = off[g] + g;
    int L  = off[g + 1] - off[g] + 1;
    if (L > LP) return;                      // scalar fallback handles
    int Lpad = (L + 15) & ~15;

    const int tid = threadIdx.x;
    const char* qh_b = (const char*)(qbh + (size_t)h * T * HD);
    const char* ql_b = (const char*)(qbl + (size_t)h * T * HD);
    const char* kh_b = (const char*)(kbh + (size_t)h * T * HD);
    const char* kl_b = (const char*)(kbl + (size_t)h * T * HD);
    const char* vh_b = (const char*)(vbh + (size_t)h * T * HD);
    const char* vl_b = (const char*)(vbl + (size_t)h * T * HD);

    // pure-copy staging (rows already decomposed; q pre-scaled)
    for (int m = tid; m < Lpad; m += 256) {
        if (m < L) {
            size_t go = (size_t)(t0 + m) * 64;   // 32 bf16 = 64B per row
            #pragma unroll
            for (int g4 = 0; g4 < 4; g4++) {
                uint32_t so = (uint32_t)m * 80 + g4 * 16;
                *(uint4*)(smem + SQ_HI + so) = *(const uint4*)(qh_b + go + g4 * 16);
                *(uint4*)(smem + SQ_LO + so) = *(const uint4*)(ql_b + go + g4 * 16);
                *(uint4*)(smem + SK_HI + so) = *(const uint4*)(kh_b + go + g4 * 16);
                *(uint4*)(smem + SK_LO + so) = *(const uint4*)(kl_b + go + g4 * 16);
                *(uint4*)(smem + SV_HI + so) = *(const uint4*)(vh_b + go + g4 * 16);
                *(uint4*)(smem + SV_LO + so) = *(const uint4*)(vl_b + go + g4 * 16);
            }
        } else {
            uint4 z = make_uint4(0,0,0,0);
            #pragma unroll
            for (int g4 = 0; g4 < 4; g4++) {
                uint32_t so = (uint32_t)m * 80 + g4 * 16;
                *(uint4*)(smem + SQ_HI + so) = z; *(uint4*)(smem + SQ_LO + so) = z;
                *(uint4*)(smem + SK_HI + so) = z; *(uint4*)(smem + SK_LO + so) = z;
                *(uint4*)(smem + SV_HI + so) = z; *(uint4*)(smem + SV_LO + so) = z;
            }
        }
    }
    __syncthreads();

    const int w = tid >> 5, lane = tid & 31;
    const int lr = lane & 15, lc = lane >> 4;
    const int ntAct  = (L + 7) >> 3;         // <= 20
    const int npairs = (ntAct + 1) >> 1;     // <= 10
    const int kAct   = (L + 15) >> 4;        // <= 10
    const uint32_t vrow = ((lane >> 3) & 1) * 8 + (lane & 7);
    const uint32_t vcol = (lane >> 4) * 8;

    for (int m0 = w * 16; m0 < L; m0 += 128) {
        uint32_t qfh[2][4], qfl[2][4];
        #pragma unroll
        for (int s = 0; s < 2; s++) {
            uint32_t a = sb + SQ_HI + (uint32_t)(m0 + lr) * 80 + s * 32 + lc * 16;
            ldsm4(qfh[s], a);
            ldsm4(qfl[s], a + (SQ_LO - SQ_HI));
        }
        // S = Q @ K^T (full row in registers)
        float acc[20][4];
        #pragma unroll
        for (int t = 0; t < 20; t++) { acc[t][0]=0.f; acc[t][1]=0.f; acc[t][2]=0.f; acc[t][3]=0.f; }
        #pragma unroll 1
        for (int p = 0; p < 10; p++) {
            if (p >= npairs) break;
            #pragma unroll
            for (int s = 0; s < 2; s++) {
                uint32_t a = sb + SK_HI + (uint32_t)(p * 16 + lr) * 80 + s * 32 + lc * 16;
                uint32_t kh[4], kl[4];
                ldsm4(kh, a);
                ldsm4(kl, a + (SK_LO - SK_HI));
                uint32_t bh0[2] = {kh[0], kh[2]}, bh1[2] = {kh[1], kh[3]};
                uint32_t bl0[2] = {kl[0], kl[2]}, bl1[2] = {kl[1], kl[3]};
                mma_bf16(acc[2*p],   qfh[s], bh0);
                mma_bf16(acc[2*p],   qfh[s], bl0);
                mma_bf16(acc[2*p],   qfl[s], bh0);
                mma_bf16(acc[2*p+1], qfh[s], bh1);
                mma_bf16(acc[2*p+1], qfh[s], bl1);
                mma_bf16(acc[2*p+1], qfl[s], bh1);
            }
        }
        // softmax stats
        float mx0 = -1e30f, mx1 = -1e30f;
        #pragma unroll
        for (int t = 0; t < 20; t++) {
            if (t >= ntAct) break;
            int c = t * 8 + ((lane & 3) << 1);
            if (c >= L)     { acc[t][0] = -1e30f; acc[t][2] = -1e30f; }
            if (c + 1 >= L) { acc[t][1] = -1e30f; acc[t][3] = -1e30f; }
            mx0 = fmaxf(mx0, fmaxf(acc[t][0], acc[t][1]));
            mx1 = fmaxf(mx1, fmaxf(acc[t][2], acc[t][3]));
        }
        mx0 = fmaxf(mx0, __shfl_xor_sync(0xffffffffu, mx0, 1));
        mx0 = fmaxf(mx0, __shfl_xor_sync(0xffffffffu, mx0, 2));
        mx1 = fmaxf(mx1, __shfl_xor_sync(0xffffffffu, mx1, 1));
        mx1 = fmaxf(mx1, __shfl_xor_sync(0xffffffffu, mx1, 2));
        float s0 = 0.f, s1 = 0.f;
        #pragma unroll
        for (int t = 0; t < 20; t++) {
            if (t >= ntAct) break;
            acc[t][0] = __expf(acc[t][0] - mx0);
            acc[t][1] = __expf(acc[t][1] - mx0);
            acc[t][2] = __expf(acc[t][2] - mx1);
            acc[t][3] = __expf(acc[t][3] - mx1);
            s0 += acc[t][0] + acc[t][1];
            s1 += acc[t][2] + acc[t][3];
        }
        s0 += __shfl_xor_sync(0xffffffffu, s0, 1);
        s0 += __shfl_xor_sync(0xffffffffu, s0, 2);
        s1 += __shfl_xor_sync(0xffffffffu, s1, 1);
        s1 += __shfl_xor_sync(0xffffffffu, s1, 2);
        float i0 = 1.f / s0, i1 = 1.f / s1;

        // ctx = P @ V: convert P per k-tile and consume immediately (low reg peak)
        float cacc[4][4];
        #pragma unroll
        for (int n = 0; n < 4; n++) { cacc[n][0]=0.f; cacc[n][1]=0.f; cacc[n][2]=0.f; cacc[n][3]=0.f; }
        #pragma unroll 1
        for (int kt = 0; kt < 10; kt++) {
            if (kt >= kAct) break;
            uint32_t pfh[4], pfl[4];
            #pragma unroll
            for (int half = 0; half < 2; half++) {
                int t = 2 * kt + half;
                float p0 = 0.f, p1 = 0.f, p2 = 0.f, p3 = 0.f;
                if (t < ntAct) {
                    p0 = acc[t][0] * i0; p1 = acc[t][1] * i0;
                    p2 = acc[t][2] * i1; p3 = acc[t][3] * i1;
                }
                float h0 = bf16_rt(p0), h1 = bf16_rt(p1), h2 = bf16_rt(p2), h3 = bf16_rt(p3);
                pfh[2*half + 0] = pack_bf2(h0, h1);
                pfh[2*half + 1] = pack_bf2(h2, h3);
                pfl[2*half + 0] = pack_bf2(p0 - h0, p1 - h1);
                pfl[2*half + 1] = pack_bf2(p2 - h2, p3 - h3);
            }
            #pragma unroll
            for (int ng = 0; ng < 2; ng++) {
                uint32_t a = sb + SV_HI + (uint32_t)(kt * 16 + vrow) * 80 + (ng * 16 + vcol) * 2;
                uint32_t vh[4], vl[4];
                ldsm4t(vh, a);
                ldsm4t(vl, a + (SV_LO - SV_HI));
                uint32_t bh0[2] = {vh[0], vh[1]}, bh1[2] = {vh[2], vh[3]};
                uint32_t bl0[2] = {vl[0], vl[1]}, bl1[2] = {vl[2], vl[3]};
                mma_bf16(cacc[2*ng],   pfh, bh0);
                mma_bf16(cacc[2*ng],   pfh, bl0);
                mma_bf16(cacc[2*ng],   pfl, bh0);
                mma_bf16(cacc[2*ng+1], pfh, bh1);
                mma_bf16(cacc[2*ng+1], pfh, bl1);
                mma_bf16(cacc[2*ng+1], pfl, bh1);
            }
        }
        // store ctx decomposed token-major
        int r0 = m0 + (lane >> 2), r1 = r0 + 8;
        #pragma unroll
        for (int nt = 0; nt < 4; nt++) {
            int col = nt * 8 + ((lane & 3) << 1);
            if (r0 < L) {
                float c0 = cacc[nt][0], c1 = cacc[nt][1];
                float h0 = bf16_rt(c0), h1 = bf16_rt(c1);
                size_t o = (size_t)(t0 + r0) * EDIM + h * HD + col;
                *(uint32_t*)(ctxh + o) = pack_bf2(h0, h1);
                *(uint32_t*)(ctxl + o) = pack_bf2(c0 - h0, c1 - h1);
            }
            if (r1 < L) {
                float c0 = cacc[nt][2], c1 = cacc[nt][3];
                float h0 = bf16_rt(c0), h1 = bf16_rt(c1);
                size_t o = (size_t)(t0 + r1) * EDIM + h * HD + col;
                *(uint32_t*)(ctxh + o) = pack_bf2(h0, h1);
                *(uint32_t*)(ctxl + o) = pack_bf2(c0 - h0, c1 - h1);
            }
        }
    }
}

// ---------------- scalar fallback attention (only L > LP) ----------------
#define ATTN_SMEM (2 * LCAP * HD * 4)

__global__ __launch_bounds__(192)
void attn_kernel(const __nv_bfloat16* __restrict__ qbh, const __nv_bfloat16* __restrict__ qbl,
                 const __nv_bfloat16* __restrict__ kbh, const __nv_bfloat16* __restrict__ kbl,
                 const __nv_bfloat16* __restrict__ vbh, const __nv_bfloat16* __restrict__ vbl,
                 __nv_bfloat16* __restrict__ ctxh, __nv_bfloat16* __restrict__ ctxl,
                 const int* __restrict__ off, int T)
{
    extern __shared__ float sm[];
    float* Ks = sm;
    float* Vs = sm + LCAP * HD;

    int g = blockIdx.x, h = blockIdx.y;
    int t0 = off[g] + g;
    int L  = off[g + 1] - off[g] + 1;
    if (L <= LP) return;
    int Ls = L < LCAP ? L : LCAP;
    int tid = threadIdx.x;

    const __nv_bfloat16* kh = kbh + (size_t)h * T * HD;
    const __nv_bfloat16* kl = kbl + (size_t)h * T * HD;
    const __nv_bfloat16* vh = vbh + (size_t)h * T * HD;
    const __nv_bfloat16* vl = vbl + (size_t)h * T * HD;
    const __nv_bfloat16* qh = qbh + (size_t)h * T * HD;
    const __nv_bfloat16* ql = qbl + (size_t)h * T * HD;

    for (int idx = tid; idx < Ls * HD; idx += blockDim.x) {
        size_t o = (size_t)t0 * HD + idx;
        Ks[idx] = __bfloat162float(kh[o]) + __bfloat162float(kl[o]);
        Vs[idx] = __bfloat162float(vh[o]) + __bfloat162float(vl[o]);
    }
    __syncthreads();

    for (int qi = tid; qi < L; qi += blockDim.x) {
        float qr[32];
        size_t qo = (size_t)(t0 + qi) * HD;
        #pragma unroll
        for (int j = 0; j < 32; j++)
            qr[j] = __bfloat162float(qh[qo + j]) + __bfloat162float(ql[qo + j]);   // pre-scaled
        float mx = -1e30f, s = 0.f;
        float acc[32];
        #pragma unroll
        for (int j = 0; j < 32; j++) acc[j] = 0.f;
        for (int mk = 0; mk < L; mk++) {
            float kr[32];
            if (mk < Ls) {
                #pragma unroll
                for (int j = 0; j < 32; j++) kr[j] = Ks[mk * HD + j];
            } else {
                size_t o = (size_t)(t0 + mk) * HD;
                #pragma unroll
                for (int j = 0; j < 32; j++)
                    kr[j] = __bfloat162float(kh[o + j]) + __bfloat162float(kl[o + j]);
            }
            float d0 = 0.f, d1 = 0.f, d2 = 0.f, d3 = 0.f;
            #pragma unroll
            for (int j4 = 0; j4 < 8; j4++) {
                d0 += qr[j4*4+0] * kr[j4*4+0]; d1 += qr[j4*4+1] * kr[j4*4+1];
                d2 += qr[j4*4+2] * kr[j4*4+2]; d3 += qr[j4*4+3] * kr[j4*4+3];
            }
            float xv = (d0 + d1) + (d2 + d3);
            float p;
            if (xv > mx) {
                float c = __expf(mx - xv);
                s *= c;
                #pragma unroll
                for (int j = 0; j < 32; j++) acc[j] *= c;
                mx = xv; p = 1.f;
            } else p = __expf(xv - mx);
            s += p;
            if (mk < Ls) {
                #pragma unroll
                for (int j = 0; j < 32; j++) acc[j] += p * Vs[mk * HD + j];
            } else {
                size_t o = (size_t)(t0 + mk) * HD;
                #pragma unroll
                for (int j = 0; j < 32; j++)
                    acc[j] += p * (__bfloat162float(vh[o + j]) + __bfloat162float(vl[o + j]));
            }
        }
        float inv = 1.f / s;
        size_t co = (size_t)(t0 + qi) * EDIM + h * HD;
        #pragma unroll
        for (int j2 = 0; j2 < 16; j2++) {
            float c0 = acc[j2*2+0] * inv, c1 = acc[j2*2+1] * inv;
            float h0 = bf16_rt(c0), h1 = bf16_rt(c1);
            *(uint32_t*)(ctxh + co + j2*2) = pack_bf2(h0, h1);
            *(uint32_t*)(ctxl + co + j2*2) = pack_bf2(c0 - h0, c1 - h1);
        }
    }
}

// ---------------- launch ----------------
extern "C" void kernel_launch(void* const* d_in, const int* in_sizes, int n_in,
                              void* d_out, int out_size)
{
    const float* x       = (const float*)d_in[0];
    const float* metal_x = (const float*)d_in[1];
    const int*   batch   = (const int*)  d_in[2];
    const float* Wk      = (const float*)d_in[3];
    const float* bk      = (const float*)d_in[4];
    const float* Wq      = (const float*)d_in[5];
    const float* bq      = (const float*)d_in[6];
    const float* in_w    = (const float*)d_in[7];
    const float* in_b    = (const float*)d_in[8];
    const float* out_w   = (const float*)d_in[9];
    const float* out_b   = (const float*)d_in[10];
    float* out = (float*)d_out;

    int N  = in_sizes[0] / EDIM;
    int nB = in_sizes[1] / EDIM;
    int T  = N + nB;

    float* value;
    __nv_bfloat16 *kinh, *kinl, *qinh, *qinl, *qbh, *qbl, *kbh, *kbl, *vbh, *vbl, *ctxh, *ctxl, *wbhi, *wblo;
    int *off, *dest;
    cudaGetSymbolAddress((void**)&value, g_value);
    cudaGetSymbolAddress((void**)&kinh,  g_kinh);
    cudaGetSymbolAddress((void**)&kinl,  g_kinl);
    cudaGetSymbolAddress((void**)&qinh,  g_qinh);
    cudaGetSymbolAddress((void**)&qinl,  g_qinl);
    cudaGetSymbolAddress((void**)&qbh,   g_qbh);
    cudaGetSymbolAddress((void**)&qbl,   g_qbl);
    cudaGetSymbolAddress((void**)&kbh,   g_kbh);
    cudaGetSymbolAddress((void**)&kbl,   g_kbl);
    cudaGetSymbolAddress((void**)&vbh,   g_vbh);
    cudaGetSymbolAddress((void**)&vbl,   g_vbl);
    cudaGetSymbolAddress((void**)&ctxh,  g_ctxh);
    cudaGetSymbolAddress((void**)&ctxl,  g_ctxl);
    cudaGetSymbolAddress((void**)&wbhi,  g_wbhi);
    cudaGetSymbolAddress((void**)&wblo,  g_wblo);
    cudaGetSymbolAddress((void**)&off,   g_off);
    cudaGetSymbolAddress((void**)&dest,  g_dest);

    cudaFuncSetAttribute(gemm_fused3,    cudaFuncAttributeMaxDynamicSharedMemorySize, GEMM_SMEM);
    cudaFuncSetAttribute(gemm_singleH,   cudaFuncAttributeMaxDynamicSharedMemorySize, GEMM_SMEM);
    cudaFuncSetAttribute(gemm_singleOut, cudaFuncAttributeMaxDynamicSharedMemorySize, GEMM_SMEM);
    cudaFuncSetAttribute(attn_tc_kernel, cudaFuncAttributeMaxDynamicSharedMemorySize, ATTN_TC_SMEM);
    cudaFuncSetAttribute(attn_kernel,    cudaFuncAttributeMaxDynamicSharedMemorySize, ATTN_SMEM);

    const int W = EDIM * EDIM;
    const float SCALE = 0.17677669529663688f;   // 1/sqrt(32)

    offsets_kernel<<<(nB + 256) / 256, 256>>>(batch, N, nB, off);
    wdecomp_kernel<<<(6 * W + 255) / 256, 256>>>(Wk, Wq, in_w, out_w, wbhi, wblo);
    gather_kernel<<<(T + 7) / 8, 256>>>(x, metal_x, batch, off, N, nB, value, dest);

    int tiles = (T + 63) / 64;

    // value -> kin, qin (decomposed), v (head-major decomposed)
    gemm_fused3<<<tiles, 256, GEMM_SMEM>>>(value,
        wbhi,       wblo,          // Wk
        wbhi + 1*W, wblo + 1*W,    // Wq
        wbhi + 4*W, wblo + 4*W,    // in_v
        bk, bq, in_b + 256,
        kinh, kinl, qinh, qinl, vbh, vbl, T);

    // qin -> q (scaled), kin -> k (head-major decomposed)
    gemm_singleH<<<tiles, 256, GEMM_SMEM>>>(qinh, qinl, wbhi + 2*W, wblo + 2*W, in_b,       qbh, qbl, T, SCALE);
    gemm_singleH<<<tiles, 256, GEMM_SMEM>>>(kinh, kinl, wbhi + 3*W, wblo + 3*W, in_b + 128, kbh, kbl, T, 1.0f);

    dim3 agrid(nB, NHEAD);
    attn_tc_kernel<<<agrid, 256, ATTN_TC_SMEM>>>(qbh, qbl, kbh, kbl, vbh, vbl, ctxh, ctxl, off, T);
    attn_kernel<<<agrid, 192, ATTN_SMEM>>>(qbh, qbl, kbh, kbl, vbh, vbl, ctxh, ctxl, off, T);

    // ctx -> out (dest scatter)
    gemm_singleOut<<<tiles, 256, GEMM_SMEM>>>(ctxh, ctxl, wbhi + 5*W, wblo + 5*W, out_b, out, dest, T);
}